// round 1
// baseline (speedup 1.0000x reference)
#include <cuda_runtime.h>
#include <cstdint>

#define M_ROWS 4096
#define N_HID  16384
#define K_DIM  768
#define K_SPARSE 32
#define MAX_ACT 64

// ---------------- scratch (device globals; no allocation allowed) ----------------
__device__ int   g_cnt[M_ROWS];
__device__ int   g_idx[M_ROWS * MAX_ACT];
__device__ float g_val[M_ROWS * MAX_ACT];
__device__ float g_invnorm[N_HID];

// ---------------- encoder GEMM: pre[m][n] = sum_k x[m][k]*W[n][k] + b[n] --------
// 128x128 block tile, BK=8, 256 threads, 8x8 per thread. fp32 exact.
#define BM 128
#define BN 128
#define BK 8

__global__ void __launch_bounds__(256, 2) encode_gemm(
    const float* __restrict__ X, const float* __restrict__ W,
    const float* __restrict__ bias, float* __restrict__ out)
{
    __shared__ float As[BK][BM];
    __shared__ float Bs[BK][BN];

    const int bm = blockIdx.y * BM;
    const int bn = blockIdx.x * BN;
    const int t  = threadIdx.x;
    const int tn = t & 15;   // 0..15
    const int tm = t >> 4;   // 0..15

    const int lr = t >> 1;          // 0..127 : row within tile for loads
    const int lc = (t & 1) * 4;     // 0 or 4 : k offset (float4)

    const float* Aptr = X + (size_t)(bm + lr) * K_DIM + lc;
    const float* Bptr = W + (size_t)(bn + lr) * K_DIM + lc;

    float acc[8][8];
#pragma unroll
    for (int i = 0; i < 8; i++)
#pragma unroll
        for (int j = 0; j < 8; j++) acc[i][j] = 0.0f;

    for (int k0 = 0; k0 < K_DIM; k0 += BK) {
        float4 a4 = *(const float4*)(Aptr + k0);
        float4 b4 = *(const float4*)(Bptr + k0);
        As[lc + 0][lr] = a4.x; As[lc + 1][lr] = a4.y;
        As[lc + 2][lr] = a4.z; As[lc + 3][lr] = a4.w;
        Bs[lc + 0][lr] = b4.x; Bs[lc + 1][lr] = b4.y;
        Bs[lc + 2][lr] = b4.z; Bs[lc + 3][lr] = b4.w;
        __syncthreads();

#pragma unroll
        for (int kk = 0; kk < BK; kk++) {
            float a[8], bb[8];
#pragma unroll
            for (int i = 0; i < 8; i++) a[i]  = As[kk][tm * 8 + i];
#pragma unroll
            for (int i = 0; i < 8; i++) bb[i] = Bs[kk][tn * 8 + i];
#pragma unroll
            for (int i = 0; i < 8; i++)
#pragma unroll
                for (int j = 0; j < 8; j++)
                    acc[i][j] = fmaf(a[i], bb[j], acc[i][j]);
        }
        __syncthreads();
    }

    // bias and store (bias is zeros in this problem, but keep it exact)
    float bj[8];
#pragma unroll
    for (int j = 0; j < 8; j++) bj[j] = bias[bn + tn * 8 + j];

#pragma unroll
    for (int i = 0; i < 8; i++) {
        const int m = bm + tm * 8 + i;
        float* o = out + (size_t)m * N_HID + bn + tn * 8;
        float4 o0, o1;
        o0.x = acc[i][0] + bj[0]; o0.y = acc[i][1] + bj[1];
        o0.z = acc[i][2] + bj[2]; o0.w = acc[i][3] + bj[3];
        o1.x = acc[i][4] + bj[4]; o1.y = acc[i][5] + bj[5];
        o1.z = acc[i][6] + bj[6]; o1.w = acc[i][7] + bj[7];
        *(float4*)(o + 0) = o0;
        *(float4*)(o + 4) = o1;
    }
}

// ---------------- W row inverse norms ----------------
__global__ void norm_kernel(const float* __restrict__ W)
{
    const int row  = blockIdx.x * 8 + (threadIdx.x >> 5);
    const int lane = threadIdx.x & 31;
    const float* w = W + (size_t)row * K_DIM;
    float s = 0.0f;
    for (int i = lane; i < K_DIM; i += 32) { float v = w[i]; s = fmaf(v, v, s); }
#pragma unroll
    for (int o = 16; o; o >>= 1) s += __shfl_xor_sync(0xFFFFFFFFu, s, o);
    if (lane == 0) g_invnorm[row] = rsqrtf(s);
}

// ---------------- exact top-k threshold + in-place mask ----------------
// order-preserving float -> uint32 map (larger float <-> larger uint)
__device__ __forceinline__ unsigned int f2u(float f)
{
    unsigned int b = __float_as_uint(f);
    return (b & 0x80000000u) ? ~b : (b | 0x80000000u);
}

__global__ void __launch_bounds__(256) topk_mask_kernel(float* __restrict__ enc)
{
    const int row = blockIdx.x;
    float* p = enc + (size_t)row * N_HID;
    const int t = threadIdx.x;   // 256 threads

    __shared__ unsigned int hist[256];
    __shared__ unsigned int cbuf[256];
    __shared__ unsigned int prefixSh;
    __shared__ unsigned int kSh;
    __shared__ int scnt;

    if (t == 0) { prefixSh = 0; kSh = K_SPARSE; scnt = 0; }
    __syncthreads();

    // 4 radix-select passes (MSB -> LSB) to find the exact 32nd-largest value
    for (int pass = 3; pass >= 0; --pass) {
        const int shift = pass * 8;
        hist[t] = 0;
        __syncthreads();

        const unsigned int prefix = prefixSh;
        for (int i = t; i < N_HID; i += 256) {
            const unsigned int u = f2u(p[i]);
            bool cand = (pass == 3) ||
                        ((u >> (shift + 8)) == (prefix >> (shift + 8)));
            if (cand) atomicAdd(&hist[(u >> shift) & 0xFFu], 1u);
        }
        __syncthreads();

        // suffix sums: cbuf[b] = sum_{j>=b} hist[j]
        cbuf[t] = hist[t];
        __syncthreads();
        for (int off = 1; off < 256; off <<= 1) {
            unsigned int v   = cbuf[t];
            unsigned int add = (t + off < 256) ? cbuf[t + off] : 0u;
            __syncthreads();
            cbuf[t] = v + add;
            __syncthreads();
        }

        const unsigned int kcur  = kSh;
        const unsigned int here  = cbuf[t];
        const unsigned int above = (t < 255) ? cbuf[t + 1] : 0u;
        __syncthreads();
        if (here >= kcur && above < kcur) {
            prefixSh = prefix | ((unsigned int)t << shift);
            kSh = kcur - above;
        }
        __syncthreads();
    }

    const unsigned int th = prefixSh;  // exact key of k-th largest
    for (int i = t; i < N_HID; i += 256) {
        const float v = p[i];
        const unsigned int u = f2u(v);
        if (u >= th) {
            int pos = atomicAdd(&scnt, 1);
            if (pos < MAX_ACT) {
                g_idx[row * MAX_ACT + pos] = i;
                g_val[row * MAX_ACT + pos] = v;
            }
        } else {
            p[i] = 0.0f;
        }
    }
    __syncthreads();
    if (t == 0) g_cnt[row] = (scnt > MAX_ACT) ? MAX_ACT : scnt;
}

// ---------------- sparse decoder: dec[m,:] = sum_j coef_j * W[idx_j,:] --------
__global__ void __launch_bounds__(256) decode_kernel(
    const float* __restrict__ W, float* __restrict__ dec)
{
    const int row = blockIdx.x;
    const int t = threadIdx.x;   // 256, each owns 3 output dims

    __shared__ float coef[MAX_ACT];
    __shared__ int   jrow[MAX_ACT];

    const int c = g_cnt[row];
    if (t < MAX_ACT && t < c) {
        const int j = g_idx[row * MAX_ACT + t];
        jrow[t] = j;
        coef[t] = g_val[row * MAX_ACT + t] * g_invnorm[j];
    }
    __syncthreads();

    float a0 = 0.0f, a1 = 0.0f, a2 = 0.0f;
    for (int j = 0; j < c; ++j) {
        const float* w = W + (size_t)jrow[j] * K_DIM;
        const float cf = coef[j];
        a0 = fmaf(cf, w[t],       a0);
        a1 = fmaf(cf, w[t + 256], a1);
        a2 = fmaf(cf, w[t + 512], a2);
    }
    float* o = dec + (size_t)row * K_DIM;
    o[t] = a0; o[t + 256] = a1; o[t + 512] = a2;
}

// ---------------- launch ----------------
extern "C" void kernel_launch(void* const* d_in, const int* in_sizes, int n_in,
                              void* d_out, int out_size)
{
    const float* x = (const float*)d_in[0];
    const float* W = (const float*)d_in[1];
    const float* b = (const float*)d_in[2];
    float* out = (float*)d_out;

    float* dec = out;                               // [4096, 768]
    float* enc = out + (size_t)M_ROWS * K_DIM;      // [4096, 16384]

    dim3 ggrid(N_HID / BN, M_ROWS / BM);
    encode_gemm<<<ggrid, 256>>>(x, W, b, enc);
    norm_kernel<<<N_HID / 8, 256>>>(W);
    topk_mask_kernel<<<M_ROWS, 256>>>(enc);
    decode_kernel<<<M_ROWS, 256>>>(W, dec);
}

// round 3
// speedup vs baseline: 2.5901x; 2.5901x over previous
#include <cuda_runtime.h>
#include <cstdint>

#define M_ROWS 4096
#define N_HID  16384
#define K_DIM  768
#define K_SPARSE 32
#define MAX_ACT  64
#define MAX_CAND 80
#define RANK_SEL 48

// GEMM tiling
#define BM 128
#define BN 128
#define BK 16
#define TSTRIDE 20              // floats per smem row (16 + 4 pad) -> conflict-free frags
#define NKTILE (K_DIM / BK)     // 48

// ---------------- scratch ----------------
__device__ int   g_cnt[M_ROWS];
__device__ int   g_idx[M_ROWS * MAX_ACT];
__device__ float g_val[M_ROWS * MAX_ACT];
__device__ float g_invnorm[N_HID];

// ---------------- PTX helpers ----------------
__device__ __forceinline__ uint32_t cvta_shared(const void* p) {
    return (uint32_t)__cvta_generic_to_shared(p);
}
#define CP_ASYNC16(dst, src) \
    asm volatile("cp.async.cg.shared.global [%0], [%1], 16;\n" :: "r"(dst), "l"(src))
#define CP_COMMIT() asm volatile("cp.async.commit_group;\n" ::: "memory")
#define CP_WAIT1()  asm volatile("cp.async.wait_group 1;\n" ::: "memory")
#define CP_WAIT0()  asm volatile("cp.async.wait_group 0;\n" ::: "memory")

__device__ __forceinline__ void mma_tf32(float* d, const uint32_t* a, const uint32_t* b)
{
    asm volatile(
        "mma.sync.aligned.m16n8k8.row.col.f32.tf32.tf32.f32 "
        "{%0,%1,%2,%3}, {%4,%5,%6,%7}, {%8,%9}, {%0,%1,%2,%3};\n"
        : "+f"(d[0]), "+f"(d[1]), "+f"(d[2]), "+f"(d[3])
        : "r"(a[0]), "r"(a[1]), "r"(a[2]), "r"(a[3]), "r"(b[0]), "r"(b[1]));
}

// ---------------- encoder GEMM: pre = x @ W^T + b (tf32 mma.sync) ----------------
__device__ __forceinline__ void ldtile(
    const float* __restrict__ X, const float* __restrict__ W,
    int m0, int n0, int kt, float* As, float* Bs, int tid)
{
#pragma unroll
    for (int it = 0; it < 2; it++) {
        const int g = tid + it * 256;      // 0..511 granules of 16B
        const int r = g >> 2;
        const int c = (g & 3) * 4;
        CP_ASYNC16(cvta_shared(As + r * TSTRIDE + c),
                   X + (size_t)(m0 + r) * K_DIM + kt + c);
        CP_ASYNC16(cvta_shared(Bs + r * TSTRIDE + c),
                   W + (size_t)(n0 + r) * K_DIM + kt + c);
    }
}

__global__ void __launch_bounds__(256, 2) encode_gemm(
    const float* __restrict__ X, const float* __restrict__ W,
    const float* __restrict__ bias, float* __restrict__ enc)
{
    __shared__ float As[2][BM * TSTRIDE];
    __shared__ float Bs[2][BN * TSTRIDE];

    const int t    = threadIdx.x;
    const int lane = t & 31;
    const int wid  = t >> 5;
    const int m0   = blockIdx.x * BM;
    const int n0   = blockIdx.y * BN;
    const int wm   = (wid & 1) * 64;     // warp m offset in tile
    const int wn   = (wid >> 1) * 32;    // warp n offset in tile
    const int fg   = lane >> 2;          // group id 0..7
    const int fc   = lane & 3;           // thread-in-group 0..3

    float acc[4][4][4];
#pragma unroll
    for (int i = 0; i < 4; i++)
#pragma unroll
        for (int j = 0; j < 4; j++)
#pragma unroll
            for (int r = 0; r < 4; r++) acc[i][j][r] = 0.0f;

    ldtile(X, W, m0, n0, 0, As[0], Bs[0], t);
    CP_COMMIT();

    for (int kt = 0; kt < NKTILE; kt++) {
        const int s = kt & 1;
        if (kt + 1 < NKTILE) {
            ldtile(X, W, m0, n0, (kt + 1) * BK, As[s ^ 1], Bs[s ^ 1], t);
            CP_COMMIT();
            CP_WAIT1();
        } else {
            CP_WAIT0();
        }
        __syncthreads();

        const uint32_t* Au = (const uint32_t*)As[s];
        const uint32_t* Bu = (const uint32_t*)Bs[s];
#pragma unroll
        for (int ks = 0; ks < BK; ks += 8) {
            uint32_t a[4][4], b[4][2];
#pragma unroll
            for (int mi = 0; mi < 4; mi++) {
                const uint32_t* ap = Au + (wm + mi * 16) * TSTRIDE + ks;
                a[mi][0] = ap[fg * TSTRIDE + fc];
                a[mi][1] = ap[(fg + 8) * TSTRIDE + fc];
                a[mi][2] = ap[fg * TSTRIDE + fc + 4];
                a[mi][3] = ap[(fg + 8) * TSTRIDE + fc + 4];
            }
#pragma unroll
            for (int nj = 0; nj < 4; nj++) {
                const uint32_t* bp = Bu + (wn + nj * 8 + fg) * TSTRIDE + ks;
                b[nj][0] = bp[fc];
                b[nj][1] = bp[fc + 4];
            }
#pragma unroll
            for (int mi = 0; mi < 4; mi++)
#pragma unroll
                for (int nj = 0; nj < 4; nj++)
                    mma_tf32(acc[mi][nj], a[mi], b[nj]);
        }
        __syncthreads();
    }

    // epilogue: direct st.64 per fragment half-row
#pragma unroll
    for (int nj = 0; nj < 4; nj++) {
        const int col = n0 + wn + nj * 8 + fc * 2;
        const float b0 = bias[col], b1 = bias[col + 1];
#pragma unroll
        for (int mi = 0; mi < 4; mi++) {
            const int row = m0 + wm + mi * 16 + fg;
            float2 v0 = make_float2(acc[mi][nj][0] + b0, acc[mi][nj][1] + b1);
            float2 v1 = make_float2(acc[mi][nj][2] + b0, acc[mi][nj][3] + b1);
            *(float2*)(enc + (size_t)row * N_HID + col)       = v0;
            *(float2*)(enc + (size_t)(row + 8) * N_HID + col) = v1;
        }
    }
}

// ---------------- W row inverse norms ----------------
__global__ void norm_kernel(const float* __restrict__ W)
{
    const int row  = blockIdx.x * 8 + (threadIdx.x >> 5);
    const int lane = threadIdx.x & 31;
    const float* w = W + (size_t)row * K_DIM;
    float s = 0.0f;
    for (int i = lane; i < K_DIM; i += 32) { float v = w[i]; s = fmaf(v, v, s); }
#pragma unroll
    for (int o = 16; o; o >>= 1) s += __shfl_xor_sync(0xFFFFFFFFu, s, o);
    if (lane == 0) g_invnorm[row] = rsqrtf(s);
}

// ---------------- top-k with exact fp32 fixup ----------------
__device__ __forceinline__ unsigned int f2u(float f)
{
    unsigned int b = __float_as_uint(f);
    return (b & 0x80000000u) ? ~b : (b | 0x80000000u);
}

__global__ void __launch_bounds__(256) topk_fix_kernel(
    const float* __restrict__ X, const float* __restrict__ W,
    const float* __restrict__ bias, float* __restrict__ enc)
{
    const int row = blockIdx.x;
    float* p = enc + (size_t)row * N_HID;
    const int t = threadIdx.x;

    __shared__ float xrow[K_DIM];
    __shared__ unsigned int hist[256];
    __shared__ unsigned int cbuf[256];
    __shared__ unsigned int prefixSh, kSh;
    __shared__ int ncand, nsel;
    __shared__ int   cidx[MAX_CAND];
    __shared__ float cval[MAX_CAND];

    for (int i = t; i < K_DIM; i += 256) xrow[i] = X[(size_t)row * K_DIM + i];
    if (t == 0) { prefixSh = 0; kSh = RANK_SEL; ncand = 0; nsel = 0; }
    __syncthreads();

    // radix select: exact key of rank-RANK_SEL on approximate values
    for (int pass = 3; pass >= 0; --pass) {
        const int shift = pass * 8;
        hist[t] = 0;
        __syncthreads();
        const unsigned int prefix = prefixSh;
        for (int i = t; i < N_HID; i += 256) {
            const unsigned int u = f2u(p[i]);
            bool cand = (pass == 3) || ((u >> (shift + 8)) == (prefix >> (shift + 8)));
            if (cand) atomicAdd(&hist[(u >> shift) & 0xFFu], 1u);
        }
        __syncthreads();
        cbuf[t] = hist[t];
        __syncthreads();
        for (int off = 1; off < 256; off <<= 1) {
            unsigned int v   = cbuf[t];
            unsigned int add = (t + off < 256) ? cbuf[t + off] : 0u;
            __syncthreads();
            cbuf[t] = v + add;
            __syncthreads();
        }
        const unsigned int kcur  = kSh;
        const unsigned int here  = cbuf[t];
        const unsigned int above = (t < 255) ? cbuf[t + 1] : 0u;
        __syncthreads();
        if (here >= kcur && above < kcur) {
            prefixSh = prefix | ((unsigned int)t << shift);
            kSh = kcur - above;
        }
        __syncthreads();
    }

    // collect candidate indices (approx top-RANK_SEL superset)
    const unsigned int th = prefixSh;
    for (int i = t; i < N_HID; i += 256) {
        if (f2u(p[i]) >= th) {
            int q = atomicAdd(&ncand, 1);
            if (q < MAX_CAND) cidx[q] = i;
        }
    }
    __syncthreads();
    const int nc = (ncand < MAX_CAND) ? ncand : MAX_CAND;

    // exact fp32 dot products for candidates (one warp per candidate)
    const int lane = t & 31, w = t >> 5;
    for (int i = w; i < nc; i += 8) {
        const float* wr = W + (size_t)cidx[i] * K_DIM;
        float s = 0.0f;
        for (int j = lane; j < K_DIM; j += 32) s = fmaf(xrow[j], wr[j], s);
#pragma unroll
        for (int o = 16; o; o >>= 1) s += __shfl_xor_sync(0xFFFFFFFFu, s, o);
        if (lane == 0) cval[i] = s + bias[cidx[i]];
    }
    __syncthreads();

    // zero the whole row (overwrites approximate values)
    float4 z4 = make_float4(0.f, 0.f, 0.f, 0.f);
    for (int i = t; i < N_HID / 4; i += 256) ((float4*)p)[i] = z4;
    __syncthreads();

    // exact rank among candidates; keep if fewer than K_SPARSE strictly greater
    // (keeps ties at the threshold, matching `pre >= thresh`)
    if (t < nc) {
        const float v = cval[t];
        int cnt = 0;
        for (int j = 0; j < nc; j++) cnt += (cval[j] > v);
        if (cnt < K_SPARSE) {
            p[cidx[t]] = v;
            int q = atomicAdd(&nsel, 1);
            if (q < MAX_ACT) {
                g_idx[row * MAX_ACT + q] = cidx[t];
                g_val[row * MAX_ACT + q] = v;
            }
        }
    }
    __syncthreads();
    if (t == 0) g_cnt[row] = (nsel > MAX_ACT) ? MAX_ACT : nsel;
}

// ---------------- sparse decoder ----------------
__global__ void __launch_bounds__(256) decode_kernel(
    const float* __restrict__ W, float* __restrict__ dec)
{
    const int row = blockIdx.x;
    const int t = threadIdx.x;

    __shared__ float coef[MAX_ACT];
    __shared__ int   jrow[MAX_ACT];

    const int c = g_cnt[row];
    if (t < MAX_ACT && t < c) {
        const int j = g_idx[row * MAX_ACT + t];
        jrow[t] = j;
        coef[t] = g_val[row * MAX_ACT + t] * g_invnorm[j];
    }
    __syncthreads();

    float a0 = 0.0f, a1 = 0.0f, a2 = 0.0f;
    for (int j = 0; j < c; ++j) {
        const float* w = W + (size_t)jrow[j] * K_DIM;
        const float cf = coef[j];
        a0 = fmaf(cf, w[t],       a0);
        a1 = fmaf(cf, w[t + 256], a1);
        a2 = fmaf(cf, w[t + 512], a2);
    }
    float* o = dec + (size_t)row * K_DIM;
    o[t] = a0; o[t + 256] = a1; o[t + 512] = a2;
}

// ---------------- launch ----------------
extern "C" void kernel_launch(void* const* d_in, const int* in_sizes, int n_in,
                              void* d_out, int out_size)
{
    const float* x = (const float*)d_in[0];
    const float* W = (const float*)d_in[1];
    const float* b = (const float*)d_in[2];
    float* out = (float*)d_out;

    float* dec = out;                               // [4096, 768]
    float* enc = out + (size_t)M_ROWS * K_DIM;      // [4096, 16384]

    dim3 ggrid(M_ROWS / BM, N_HID / BN);            // x fast: consecutive CTAs share B tile
    encode_gemm<<<ggrid, 256>>>(x, W, b, enc);
    norm_kernel<<<N_HID / 8, 256>>>(W);
    topk_fix_kernel<<<M_ROWS, 256>>>(x, W, b, enc);
    decode_kernel<<<M_ROWS, 256>>>(W, dec);
}

// round 4
// speedup vs baseline: 2.7757x; 1.0717x over previous
#include <cuda_runtime.h>
#include <cuda_bf16.h>
#include <cstdint>

#define M_ROWS 4096
#define N_HID  16384
#define K_DIM  768
#define K_SPARSE 32
#define MAX_ACT  64
#define MAX_CAND 96
#define RANK_SEL 48
#define CAP      2048
#define THRESH   1.5f

// GEMM tiling: 128x128 CTA tile, BK=32 bf16 (16 words), double-buffered
#define BKW 16                 // words (4B) per smem row
#define TS  20                 // padded word stride
#define NKTILE (K_DIM / 32)    // 24

// ---------------- device scratch ----------------
__device__ __nv_bfloat16 X16[M_ROWS * K_DIM];
__device__ __nv_bfloat16 W16[N_HID * K_DIM];
__device__ int   g_ccnt[M_ROWS];
__device__ int   g_cidx[(size_t)M_ROWS * CAP];
__device__ float g_cval[(size_t)M_ROWS * CAP];
__device__ int   g_cnt[M_ROWS];
__device__ int   g_idx[M_ROWS * MAX_ACT];
__device__ float g_val[M_ROWS * MAX_ACT];
__device__ float g_invnorm[N_HID];

// ---------------- PTX helpers ----------------
__device__ __forceinline__ uint32_t cvta_shared(const void* p) {
    return (uint32_t)__cvta_generic_to_shared(p);
}
#define CP_ASYNC16(dst, src) \
    asm volatile("cp.async.cg.shared.global [%0], [%1], 16;\n" :: "r"(dst), "l"(src))
#define CP_COMMIT() asm volatile("cp.async.commit_group;\n" ::: "memory")
#define CP_WAIT1()  asm volatile("cp.async.wait_group 1;\n" ::: "memory")
#define CP_WAIT0()  asm volatile("cp.async.wait_group 0;\n" ::: "memory")

__device__ __forceinline__ void mma_bf16(float* d, const uint32_t* a, const uint32_t* b)
{
    asm volatile(
        "mma.sync.aligned.m16n8k16.row.col.f32.bf16.bf16.f32 "
        "{%0,%1,%2,%3}, {%4,%5,%6,%7}, {%8,%9}, {%0,%1,%2,%3};\n"
        : "+f"(d[0]), "+f"(d[1]), "+f"(d[2]), "+f"(d[3])
        : "r"(a[0]), "r"(a[1]), "r"(a[2]), "r"(a[3]), "r"(b[0]), "r"(b[1]));
}

// ---------------- conversion kernels ----------------
__global__ void convert_x_kernel(const float* __restrict__ X)
{
    const int i = blockIdx.x * 256 + threadIdx.x;
    if (i < M_ROWS * K_DIM) X16[i] = __float2bfloat16(X[i]);
    if (i < M_ROWS) g_ccnt[i] = 0;
}

__global__ void convert_w_kernel(const float* __restrict__ W)
{
    const int row  = blockIdx.x * 8 + (threadIdx.x >> 5);
    const int lane = threadIdx.x & 31;
    const float* w = W + (size_t)row * K_DIM;
    float s = 0.0f;
    for (int i = lane; i < K_DIM; i += 32) {
        const float v = w[i];
        s = fmaf(v, v, s);
        W16[(size_t)row * K_DIM + i] = __float2bfloat16(v);
    }
#pragma unroll
    for (int o = 16; o; o >>= 1) s += __shfl_xor_sync(0xFFFFFFFFu, s, o);
    if (lane == 0) g_invnorm[row] = rsqrtf(s);
}

// ---------------- encoder GEMM (bf16 mma.sync), candidate-append epilogue ------
__device__ __forceinline__ void ldtile16(int m0, int n0, int kt,
                                         uint32_t* As, uint32_t* Bs, int t)
{
#pragma unroll
    for (int it = 0; it < 2; it++) {
        const int g = t + it * 256;          // 0..511
        const int r = g >> 2;                // 0..127
        const int c = g & 3;                 // 16B granule
        CP_ASYNC16(cvta_shared(As + r * TS + c * 4),
                   X16 + (size_t)(m0 + r) * K_DIM + kt + c * 8);
        CP_ASYNC16(cvta_shared(Bs + r * TS + c * 4),
                   W16 + (size_t)(n0 + r) * K_DIM + kt + c * 8);
    }
}

__device__ __forceinline__ void cand_append(int row, int col, float v)
{
    if (v > THRESH) {
        const int q = atomicAdd(&g_ccnt[row], 1);
        if (q < CAP) {
            g_cidx[(size_t)row * CAP + q] = col;
            g_cval[(size_t)row * CAP + q] = v;
        }
    }
}

__global__ void __launch_bounds__(256, 2) encode_gemm(const float* __restrict__ bias)
{
    __shared__ uint32_t As[2][128 * TS];
    __shared__ uint32_t Bs[2][128 * TS];

    const int t    = threadIdx.x;
    const int lane = t & 31;
    const int wid  = t >> 5;
    const int m0   = blockIdx.x * 128;
    const int n0   = blockIdx.y * 128;
    const int wm   = (wid & 1) * 64;
    const int wn   = (wid >> 1) * 32;
    const int fg   = lane >> 2;
    const int fc   = lane & 3;

    float acc[4][4][4];
#pragma unroll
    for (int i = 0; i < 4; i++)
#pragma unroll
        for (int j = 0; j < 4; j++)
#pragma unroll
            for (int r = 0; r < 4; r++) acc[i][j][r] = 0.0f;

    ldtile16(m0, n0, 0, As[0], Bs[0], t);
    CP_COMMIT();

    for (int kt = 0; kt < NKTILE; kt++) {
        const int s = kt & 1;
        if (kt + 1 < NKTILE) {
            ldtile16(m0, n0, (kt + 1) * 32, As[s ^ 1], Bs[s ^ 1], t);
            CP_COMMIT();
            CP_WAIT1();
        } else {
            CP_WAIT0();
        }
        __syncthreads();

        const uint32_t* Au = As[s];
        const uint32_t* Bu = Bs[s];
#pragma unroll
        for (int ks = 0; ks < BKW; ks += 8) {
            uint32_t a[4][4], b[4][2];
#pragma unroll
            for (int mi = 0; mi < 4; mi++) {
                const uint32_t* ap = Au + (wm + mi * 16) * TS + ks;
                a[mi][0] = ap[fg * TS + fc];
                a[mi][1] = ap[(fg + 8) * TS + fc];
                a[mi][2] = ap[fg * TS + fc + 4];
                a[mi][3] = ap[(fg + 8) * TS + fc + 4];
            }
#pragma unroll
            for (int nj = 0; nj < 4; nj++) {
                const uint32_t* bp = Bu + (wn + nj * 8 + fg) * TS + ks;
                b[nj][0] = bp[fc];
                b[nj][1] = bp[fc + 4];
            }
#pragma unroll
            for (int mi = 0; mi < 4; mi++)
#pragma unroll
                for (int nj = 0; nj < 4; nj++)
                    mma_bf16(acc[mi][nj], a[mi], b[nj]);
        }
        __syncthreads();
    }

    // epilogue: threshold + append candidates (no dense store)
#pragma unroll
    for (int nj = 0; nj < 4; nj++) {
        const int col = n0 + wn + nj * 8 + fc * 2;
        const float b0 = bias[col], b1 = bias[col + 1];
#pragma unroll
        for (int mi = 0; mi < 4; mi++) {
            const int row = m0 + wm + mi * 16 + fg;
            cand_append(row,     col,     acc[mi][nj][0] + b0);
            cand_append(row,     col + 1, acc[mi][nj][1] + b1);
            cand_append(row + 8, col,     acc[mi][nj][2] + b0);
            cand_append(row + 8, col + 1, acc[mi][nj][3] + b1);
        }
    }
}

// ---------------- top-k fixup ----------------
__device__ __forceinline__ unsigned int f2u(float f)
{
    unsigned int b = __float_as_uint(f);
    return (b & 0x80000000u) ? ~b : (b | 0x80000000u);
}

// exact key of k-th largest over arr[0..n), 256-thread block collective
__device__ unsigned int radix_key(const float* arr, int n, int k,
                                  unsigned int* hist, unsigned int* cbuf,
                                  unsigned int* prefixSh, unsigned int* kSh, int t)
{
    if (t == 0) { *prefixSh = 0; *kSh = (unsigned int)k; }
    __syncthreads();
    for (int pass = 3; pass >= 0; --pass) {
        const int shift = pass * 8;
        hist[t] = 0;
        __syncthreads();
        const unsigned int prefix = *prefixSh;
        for (int i = t; i < n; i += 256) {
            const unsigned int u = f2u(arr[i]);
            bool cand = (pass == 3) || ((u >> (shift + 8)) == (prefix >> (shift + 8)));
            if (cand) atomicAdd(&hist[(u >> shift) & 0xFFu], 1u);
        }
        __syncthreads();
        cbuf[t] = hist[t];
        __syncthreads();
        for (int off = 1; off < 256; off <<= 1) {
            unsigned int v   = cbuf[t];
            unsigned int add = (t + off < 256) ? cbuf[t + off] : 0u;
            __syncthreads();
            cbuf[t] = v + add;
            __syncthreads();
        }
        const unsigned int kcur  = *kSh;
        const unsigned int here  = cbuf[t];
        const unsigned int above = (t < 255) ? cbuf[t + 1] : 0u;
        __syncthreads();
        if (here >= kcur && above < kcur) {
            *prefixSh = prefix | ((unsigned int)t << shift);
            *kSh = kcur - above;
        }
        __syncthreads();
    }
    return *prefixSh;
}

__global__ void __launch_bounds__(256) fixup_kernel(
    const float* __restrict__ X, const float* __restrict__ W,
    const float* __restrict__ bias, float* __restrict__ enc)
{
    const int row = blockIdx.x;
    float* p = enc + (size_t)row * N_HID;
    const int t = threadIdx.x;

    __shared__ float xrow[K_DIM];
    __shared__ float cval_s[CAP];
    __shared__ unsigned int hist[256], cbuf[256];
    __shared__ unsigned int prefixSh, kSh;
    __shared__ int nsel2, nfin;
    __shared__ int   sel_i[MAX_CAND];
    __shared__ float sel_v[MAX_CAND];

    for (int i = t; i < K_DIM; i += 256) xrow[i] = X[(size_t)row * K_DIM + i];
    if (t == 0) { nsel2 = 0; nfin = 0; }

    // zero this output row
    float4 z4 = make_float4(0.f, 0.f, 0.f, 0.f);
    float4* p4 = (float4*)p;
    for (int i = t; i < N_HID / 4; i += 256) p4[i] = z4;
    __syncthreads();

    const int cnt = g_ccnt[row];
    if (cnt >= RANK_SEL && cnt <= CAP) {
        for (int i = t; i < cnt; i += 256) cval_s[i] = g_cval[(size_t)row * CAP + i];
        __syncthreads();
        const unsigned int key = radix_key(cval_s, cnt, RANK_SEL,
                                           hist, cbuf, &prefixSh, &kSh, t);
        for (int i = t; i < cnt; i += 256) {
            if (f2u(cval_s[i]) >= key) {
                const int q = atomicAdd(&nsel2, 1);
                if (q < MAX_CAND) sel_i[q] = g_cidx[(size_t)row * CAP + i];
            }
        }
    } else {
        // fallback (statistically never taken): exact full-row recompute
        for (int n = t; n < N_HID; n += 256) {
            const float* wr = W + (size_t)n * K_DIM;
            float s = 0.0f;
            for (int k2 = 0; k2 < K_DIM; k2++) s = fmaf(xrow[k2], wr[k2], s);
            p[n] = s + bias[n];
        }
        __syncthreads();
        const unsigned int key = radix_key(p, N_HID, RANK_SEL,
                                           hist, cbuf, &prefixSh, &kSh, t);
        for (int i = t; i < N_HID; i += 256) {
            if (f2u(p[i]) >= key) {
                const int q = atomicAdd(&nsel2, 1);
                if (q < MAX_CAND) sel_i[q] = i;
            }
        }
        __syncthreads();
        for (int i = t; i < N_HID / 4; i += 256) p4[i] = z4;   // re-zero
    }
    __syncthreads();
    const int nc = (nsel2 < MAX_CAND) ? nsel2 : MAX_CAND;

    // exact fp32 dot products for candidates (one warp per candidate)
    const int lane = t & 31, w = t >> 5;
    for (int i = w; i < nc; i += 8) {
        const float* wr = W + (size_t)sel_i[i] * K_DIM;
        float s = 0.0f;
        for (int j = lane; j < K_DIM; j += 32) s = fmaf(xrow[j], wr[j], s);
#pragma unroll
        for (int o = 16; o; o >>= 1) s += __shfl_xor_sync(0xFFFFFFFFu, s, o);
        if (lane == 0) sel_v[i] = s + bias[sel_i[i]];
    }
    __syncthreads();

    // exact rank; keep if fewer than K_SPARSE strictly greater (keeps ties)
    if (t < nc) {
        const float v = sel_v[t];
        int cg = 0;
        for (int j = 0; j < nc; j++) cg += (sel_v[j] > v);
        if (cg < K_SPARSE) {
            p[sel_i[t]] = v;
            const int q = atomicAdd(&nfin, 1);
            if (q < MAX_ACT) {
                g_idx[row * MAX_ACT + q] = sel_i[t];
                g_val[row * MAX_ACT + q] = v;
            }
        }
    }
    __syncthreads();
    if (t == 0) g_cnt[row] = (nfin > MAX_ACT) ? MAX_ACT : nfin;
}

// ---------------- sparse decoder ----------------
__global__ void __launch_bounds__(256) decode_kernel(
    const float* __restrict__ W, float* __restrict__ dec)
{
    const int row = blockIdx.x;
    const int t = threadIdx.x;

    __shared__ float coef[MAX_ACT];
    __shared__ int   jrow[MAX_ACT];

    const int c = g_cnt[row];
    if (t < MAX_ACT && t < c) {
        const int j = g_idx[row * MAX_ACT + t];
        jrow[t] = j;
        coef[t] = g_val[row * MAX_ACT + t] * g_invnorm[j];
    }
    __syncthreads();

    float a0 = 0.0f, a1 = 0.0f, a2 = 0.0f;
    for (int j = 0; j < c; ++j) {
        const float* w = W + (size_t)jrow[j] * K_DIM;
        const float cf = coef[j];
        a0 = fmaf(cf, w[t],       a0);
        a1 = fmaf(cf, w[t + 256], a1);
        a2 = fmaf(cf, w[t + 512], a2);
    }
    float* o = dec + (size_t)row * K_DIM;
    o[t] = a0; o[t + 256] = a1; o[t + 512] = a2;
}

// ---------------- launch ----------------
extern "C" void kernel_launch(void* const* d_in, const int* in_sizes, int n_in,
                              void* d_out, int out_size)
{
    const float* x = (const float*)d_in[0];
    const float* W = (const float*)d_in[1];
    const float* b = (const float*)d_in[2];
    float* out = (float*)d_out;

    float* dec = out;                               // [4096, 768]
    float* enc = out + (size_t)M_ROWS * K_DIM;      // [4096, 16384]

    convert_x_kernel<<<(M_ROWS * K_DIM + 255) / 256, 256>>>(x);
    convert_w_kernel<<<N_HID / 8, 256>>>(W);

    dim3 ggrid(M_ROWS / 128, N_HID / 128);          // x fast: consecutive CTAs share B tile
    encode_gemm<<<ggrid, 256>>>(b);
    fixup_kernel<<<M_ROWS, 256>>>(x, W, b, enc);
    decode_kernel<<<M_ROWS, 256>>>(W, dec);
}

// round 5
// speedup vs baseline: 2.8131x; 1.0135x over previous
#include <cuda_runtime.h>
#include <cstdint>

#define M_ROWS 4096
#define N_HID  16384
#define K_DIM  768
#define K_SPARSE 32
#define MAX_ACT  64
#define MAX_CAND 96
#define RANK_SEL 64
#define CAP      1024
#define THRESH   2.0f

// int8 quantization scales (fixed, 5-sigma clip)
#define SX 25.4f               // 127/5.0
#define SW 703.9f              // 127/(5/sqrt(768))
#define DEQ (1.0f / (SX * SW))

// GEMM tiling: 128x128 CTA tile, BK=64 int8 (16 words), double-buffered
#define TS  20                 // padded word stride (64B row -> 16 words + 4 pad)
#define NKTILE (K_DIM / 64)    // 12

// ---------------- device scratch ----------------
__device__ int8_t Xq[M_ROWS * K_DIM];
__device__ int8_t Wq[N_HID * K_DIM];
__device__ int   g_ccnt[M_ROWS];
__device__ int   g_cidx[(size_t)M_ROWS * CAP];
__device__ float g_cval[(size_t)M_ROWS * CAP];
__device__ int   g_cnt[M_ROWS];
__device__ int   g_idx[M_ROWS * MAX_ACT];
__device__ float g_val[M_ROWS * MAX_ACT];
__device__ float g_invnorm[N_HID];

// ---------------- PTX helpers ----------------
__device__ __forceinline__ uint32_t cvta_shared(const void* p) {
    return (uint32_t)__cvta_generic_to_shared(p);
}
#define CP_ASYNC16(dst, src) \
    asm volatile("cp.async.cg.shared.global [%0], [%1], 16;\n" :: "r"(dst), "l"(src))
#define CP_COMMIT() asm volatile("cp.async.commit_group;\n" ::: "memory")
#define CP_WAIT1()  asm volatile("cp.async.wait_group 1;\n" ::: "memory")
#define CP_WAIT0()  asm volatile("cp.async.wait_group 0;\n" ::: "memory")

__device__ __forceinline__ void mma_s8(int* d, const uint32_t* a, const uint32_t* b)
{
    asm volatile(
        "mma.sync.aligned.m16n8k32.row.col.s32.s8.s8.s32 "
        "{%0,%1,%2,%3}, {%4,%5,%6,%7}, {%8,%9}, {%0,%1,%2,%3};\n"
        : "+r"(d[0]), "+r"(d[1]), "+r"(d[2]), "+r"(d[3])
        : "r"(a[0]), "r"(a[1]), "r"(a[2]), "r"(a[3]), "r"(b[0]), "r"(b[1]));
}

__device__ __forceinline__ int8_t q8(float v, float s)
{
    float t = v * s;
    t = fminf(fmaxf(t, -127.0f), 127.0f);
    return (int8_t)__float2int_rn(t);
}

// ---------------- quantize kernels ----------------
__global__ void quant_x_kernel(const float* __restrict__ X)
{
    const int i = blockIdx.x * 256 + threadIdx.x;
    if (i < M_ROWS * K_DIM) Xq[i] = q8(X[i], SX);
    if (i < M_ROWS) g_ccnt[i] = 0;
}

__global__ void quant_w_kernel(const float* __restrict__ W)
{
    const int row  = blockIdx.x * 8 + (threadIdx.x >> 5);
    const int lane = threadIdx.x & 31;
    const float* w = W + (size_t)row * K_DIM;
    float s = 0.0f;
    for (int i = lane; i < K_DIM; i += 32) {
        const float v = w[i];
        s = fmaf(v, v, s);
        Wq[(size_t)row * K_DIM + i] = q8(v, SW);
    }
#pragma unroll
    for (int o = 16; o; o >>= 1) s += __shfl_xor_sync(0xFFFFFFFFu, s, o);
    if (lane == 0) g_invnorm[row] = rsqrtf(s);
}

// ---------------- zero the encoded output region ----------------
__global__ void zero_kernel(float4* __restrict__ p, int n4)
{
    const float4 z = make_float4(0.f, 0.f, 0.f, 0.f);
    for (int i = blockIdx.x * blockDim.x + threadIdx.x; i < n4;
         i += gridDim.x * blockDim.x)
        p[i] = z;
}

// ---------------- encoder GEMM (int8 mma.sync), candidate-append epilogue ------
__device__ __forceinline__ void ldtile8(int m0, int n0, int kt,
                                        uint32_t* As, uint32_t* Bs, int t)
{
#pragma uroll
#pragma unroll
    for (int it = 0; it < 2; it++) {
        const int g = t + it * 256;          // 0..511
        const int r = g >> 2;                // 0..127
        const int c = g & 3;                 // 16B granule within 64B row
        CP_ASYNC16(cvta_shared(As + r * TS + c * 4),
                   Xq + (size_t)(m0 + r) * K_DIM + kt + c * 16);
        CP_ASYNC16(cvta_shared(Bs + r * TS + c * 4),
                   Wq + (size_t)(n0 + r) * K_DIM + kt + c * 16);
    }
}

__device__ __forceinline__ void cand_append(int row, int col, float v)
{
    if (v > THRESH) {
        const int q = atomicAdd(&g_ccnt[row], 1);
        if (q < CAP) {
            g_cidx[(size_t)row * CAP + q] = col;
            g_cval[(size_t)row * CAP + q] = v;
        }
    }
}

__global__ void __launch_bounds__(256, 2) encode_gemm(const float* __restrict__ bias)
{
    __shared__ uint32_t As[2][128 * TS];
    __shared__ uint32_t Bs[2][128 * TS];

    const int t    = threadIdx.x;
    const int lane = t & 31;
    const int wid  = t >> 5;
    const int m0   = blockIdx.x * 128;
    const int n0   = blockIdx.y * 128;
    const int wm   = (wid & 1) * 64;
    const int wn   = (wid >> 1) * 32;
    const int fg   = lane >> 2;
    const int fc   = lane & 3;

    int acc[4][4][4];
#pragma unroll
    for (int i = 0; i < 4; i++)
#pragma unroll
        for (int j = 0; j < 4; j++)
#pragma unroll
            for (int r = 0; r < 4; r++) acc[i][j][r] = 0;

    ldtile8(m0, n0, 0, As[0], Bs[0], t);
    CP_COMMIT();

    for (int kt = 0; kt < NKTILE; kt++) {
        const int s = kt & 1;
        if (kt + 1 < NKTILE) {
            ldtile8(m0, n0, (kt + 1) * 64, As[s ^ 1], Bs[s ^ 1], t);
            CP_COMMIT();
            CP_WAIT1();
        } else {
            CP_WAIT0();
        }
        __syncthreads();

        const uint32_t* Au = As[s];
        const uint32_t* Bu = Bs[s];
#pragma unroll
        for (int ks = 0; ks < 16; ks += 8) {      // two k32 MMA steps per 64B tile
            uint32_t a[4][4], b[4][2];
#pragma unroll
            for (int mi = 0; mi < 4; mi++) {
                const uint32_t* ap = Au + (wm + mi * 16) * TS + ks;
                a[mi][0] = ap[fg * TS + fc];
                a[mi][1] = ap[(fg + 8) * TS + fc];
                a[mi][2] = ap[fg * TS + fc + 4];
                a[mi][3] = ap[(fg + 8) * TS + fc + 4];
            }
#pragma unroll
            for (int nj = 0; nj < 4; nj++) {
                const uint32_t* bp = Bu + (wn + nj * 8 + fg) * TS + ks;
                b[nj][0] = bp[fc];
                b[nj][1] = bp[fc + 4];
            }
#pragma unroll
            for (int mi = 0; mi < 4; mi++)
#pragma unroll
                for (int nj = 0; nj < 4; nj++)
                    mma_s8(acc[mi][nj], a[mi], b[nj]);
        }
        __syncthreads();
    }

    // epilogue: dequant + threshold + append candidates (no dense store)
#pragma unroll
    for (int nj = 0; nj < 4; nj++) {
        const int col = n0 + wn + nj * 8 + fc * 2;
        const float b0 = bias[col], b1 = bias[col + 1];
#pragma unroll
        for (int mi = 0; mi < 4; mi++) {
            const int row = m0 + wm + mi * 16 + fg;
            cand_append(row,     col,     __int2float_rn(acc[mi][nj][0]) * DEQ + b0);
            cand_append(row,     col + 1, __int2float_rn(acc[mi][nj][1]) * DEQ + b1);
            cand_append(row + 8, col,     __int2float_rn(acc[mi][nj][2]) * DEQ + b0);
            cand_append(row + 8, col + 1, __int2float_rn(acc[mi][nj][3]) * DEQ + b1);
        }
    }
}

// ---------------- top-k fixup ----------------
__device__ __forceinline__ unsigned int f2u(float f)
{
    unsigned int b = __float_as_uint(f);
    return (b & 0x80000000u) ? ~b : (b | 0x80000000u);
}

// exact key of k-th largest over arr[0..n), 256-thread block collective
__device__ unsigned int radix_key(const float* arr, int n, int k,
                                  unsigned int* hist, unsigned int* cbuf,
                                  unsigned int* prefixSh, unsigned int* kSh, int t)
{
    if (t == 0) { *prefixSh = 0; *kSh = (unsigned int)k; }
    __syncthreads();
    for (int pass = 3; pass >= 0; --pass) {
        const int shift = pass * 8;
        hist[t] = 0;
        __syncthreads();
        const unsigned int prefix = *prefixSh;
        for (int i = t; i < n; i += 256) {
            const unsigned int u = f2u(arr[i]);
            bool cand = (pass == 3) || ((u >> (shift + 8)) == (prefix >> (shift + 8)));
            if (cand) atomicAdd(&hist[(u >> shift) & 0xFFu], 1u);
        }
        __syncthreads();
        cbuf[t] = hist[t];
        __syncthreads();
        for (int off = 1; off < 256; off <<= 1) {
            unsigned int v   = cbuf[t];
            unsigned int add = (t + off < 256) ? cbuf[t + off] : 0u;
            __syncthreads();
            cbuf[t] = v + add;
            __syncthreads();
        }
        const unsigned int kcur  = *kSh;
        const unsigned int here  = cbuf[t];
        const unsigned int above = (t < 255) ? cbuf[t + 1] : 0u;
        __syncthreads();
        if (here >= kcur && above < kcur) {
            *prefixSh = prefix | ((unsigned int)t << shift);
            *kSh = kcur - above;
        }
        __syncthreads();
    }
    return *prefixSh;
}

__global__ void __launch_bounds__(256) fixup_kernel(
    const float* __restrict__ X, const float* __restrict__ W,
    const float* __restrict__ bias, float* __restrict__ enc)
{
    const int row = blockIdx.x;
    float* p = enc + (size_t)row * N_HID;
    const int t = threadIdx.x;

    __shared__ float xrow[K_DIM];
    __shared__ float cval_s[CAP];
    __shared__ unsigned int hist[256], cbuf[256];
    __shared__ unsigned int prefixSh, kSh;
    __shared__ int nsel2, nfin;
    __shared__ int   sel_i[MAX_CAND];
    __shared__ float sel_v[MAX_CAND];

    for (int i = t; i < K_DIM; i += 256) xrow[i] = X[(size_t)row * K_DIM + i];
    if (t == 0) { nsel2 = 0; nfin = 0; }
    __syncthreads();

    const int cnt = g_ccnt[row];
    if (cnt >= RANK_SEL && cnt <= CAP) {
        for (int i = t; i < cnt; i += 256) cval_s[i] = g_cval[(size_t)row * CAP + i];
        __syncthreads();
        const unsigned int key = radix_key(cval_s, cnt, RANK_SEL,
                                           hist, cbuf, &prefixSh, &kSh, t);
        for (int i = t; i < cnt; i += 256) {
            if (f2u(cval_s[i]) >= key) {
                const int q = atomicAdd(&nsel2, 1);
                if (q < MAX_CAND) sel_i[q] = g_cidx[(size_t)row * CAP + i];
            }
        }
    } else {
        // fallback (statistically never taken): exact full-row recompute
        for (int n = t; n < N_HID; n += 256) {
            const float* wr = W + (size_t)n * K_DIM;
            float s = 0.0f;
            for (int k2 = 0; k2 < K_DIM; k2++) s = fmaf(xrow[k2], wr[k2], s);
            p[n] = s + bias[n];
        }
        __syncthreads();
        const unsigned int key = radix_key(p, N_HID, RANK_SEL,
                                           hist, cbuf, &prefixSh, &kSh, t);
        for (int i = t; i < N_HID; i += 256) {
            if (f2u(p[i]) >= key) {
                const int q = atomicAdd(&nsel2, 1);
                if (q < MAX_CAND) sel_i[q] = i;
            }
        }
        __syncthreads();
        float4 z4 = make_float4(0.f, 0.f, 0.f, 0.f);
        for (int i = t; i < N_HID / 4; i += 256) ((float4*)p)[i] = z4;  // re-zero
    }
    __syncthreads();
    const int nc = (nsel2 < MAX_CAND) ? nsel2 : MAX_CAND;

    // exact fp32 dot products for selected candidates (one warp per candidate)
    const int lane = t & 31, w = t >> 5;
    for (int i = w; i < nc; i += 8) {
        const float* wr = W + (size_t)sel_i[i] * K_DIM;
        float s = 0.0f;
#pragma unroll 4
        for (int j = lane; j < K_DIM; j += 32) s = fmaf(xrow[j], wr[j], s);
#pragma unroll
        for (int o = 16; o; o >>= 1) s += __shfl_xor_sync(0xFFFFFFFFu, s, o);
        if (lane == 0) sel_v[i] = s + bias[sel_i[i]];
    }
    __syncthreads();

    // exact rank; keep if fewer than K_SPARSE strictly greater (keeps ties)
    if (t < nc) {
        const float v = sel_v[t];
        int cg = 0;
        for (int j = 0; j < nc; j++) cg += (sel_v[j] > v);
        if (cg < K_SPARSE) {
            p[sel_i[t]] = v;
            const int q = atomicAdd(&nfin, 1);
            if (q < MAX_ACT) {
                g_idx[row * MAX_ACT + q] = sel_i[t];
                g_val[row * MAX_ACT + q] = v;
            }
        }
    }
    __syncthreads();
    if (t == 0) g_cnt[row] = (nfin > MAX_ACT) ? MAX_ACT : nfin;
}

// ---------------- sparse decoder ----------------
__global__ void __launch_bounds__(256) decode_kernel(
    const float* __restrict__ W, float* __restrict__ dec)
{
    const int row = blockIdx.x;
    const int t = threadIdx.x;

    __shared__ float coef[MAX_ACT];
    __shared__ int   jrow[MAX_ACT];

    const int c = g_cnt[row];
    if (t < MAX_ACT && t < c) {
        const int j = g_idx[row * MAX_ACT + t];
        jrow[t] = j;
        coef[t] = g_val[row * MAX_ACT + t] * g_invnorm[j];
    }
    __syncthreads();

    float a0 = 0.0f, a1 = 0.0f, a2 = 0.0f;
    for (int j = 0; j < c; ++j) {
        const float* w = W + (size_t)jrow[j] * K_DIM;
        const float cf = coef[j];
        a0 = fmaf(cf, w[t],       a0);
        a1 = fmaf(cf, w[t + 256], a1);
        a2 = fmaf(cf, w[t + 512], a2);
    }
    float* o = dec + (size_t)row * K_DIM;
    o[t] = a0; o[t + 256] = a1; o[t + 512] = a2;
}

// ---------------- launch ----------------
extern "C" void kernel_launch(void* const* d_in, const int* in_sizes, int n_in,
                              void* d_out, int out_size)
{
    const float* x = (const float*)d_in[0];
    const float* W = (const float*)d_in[1];
    const float* b = (const float*)d_in[2];
    float* out = (float*)d_out;

    float* dec = out;                               // [4096, 768]
    float* enc = out + (size_t)M_ROWS * K_DIM;      // [4096, 16384]

    quant_x_kernel<<<(M_ROWS * K_DIM + 255) / 256, 256>>>(x);
    quant_w_kernel<<<N_HID / 8, 256>>>(W);
    zero_kernel<<<4096, 256>>>((float4*)enc, M_ROWS * N_HID / 4);

    dim3 ggrid(M_ROWS / 128, N_HID / 128);          // x fast: consecutive CTAs share B tile
    encode_gemm<<<ggrid, 256>>>(b);
    fixup_kernel<<<M_ROWS, 256>>>(x, W, b, enc);
    decode_kernel<<<M_ROWS, 256>>>(W, dec);
}

// round 6
// speedup vs baseline: 3.8713x; 1.3762x over previous
#include <cuda_runtime.h>
#include <cuda_bf16.h>
#include <cstdint>

#define M_ROWS 4096
#define N_HID  16384
#define K_DIM  768
#define K_SPARSE 32
#define MAX_ACT  64
#define MAX_CAND 96
#define RANK_SEL 64
#define CAP      1024
#define THRESH   2.0f

// GEMM tiling: 128x128 CTA tile, BK=32 bf16 (16 words), double-buffered
#define BKW 16                 // words (4B) per smem row
#define TS  20                 // padded word stride
#define NKTILE (K_DIM / 32)    // 24

// ---------------- device scratch ----------------
__device__ __nv_bfloat16 X16[M_ROWS * K_DIM];
__device__ __nv_bfloat16 W16[N_HID * K_DIM];
__device__ int   g_ccnt[M_ROWS];
__device__ int   g_cidx[(size_t)M_ROWS * CAP];
__device__ float g_cval[(size_t)M_ROWS * CAP];
__device__ int   g_cnt[M_ROWS];
__device__ int   g_idx[M_ROWS * MAX_ACT];
__device__ float g_val[M_ROWS * MAX_ACT];
__device__ float g_invnorm[N_HID];

// ---------------- PTX helpers ----------------
__device__ __forceinline__ uint32_t cvta_shared(const void* p) {
    return (uint32_t)__cvta_generic_to_shared(p);
}
#define CP_ASYNC16(dst, src) \
    asm volatile("cp.async.cg.shared.global [%0], [%1], 16;\n" :: "r"(dst), "l"(src))
#define CP_COMMIT() asm volatile("cp.async.commit_group;\n" ::: "memory")
#define CP_WAIT1()  asm volatile("cp.async.wait_group 1;\n" ::: "memory")
#define CP_WAIT0()  asm volatile("cp.async.wait_group 0;\n" ::: "memory")

__device__ __forceinline__ void mma_bf16(float* d, const uint32_t* a, const uint32_t* b)
{
    asm volatile(
        "mma.sync.aligned.m16n8k16.row.col.f32.bf16.bf16.f32 "
        "{%0,%1,%2,%3}, {%4,%5,%6,%7}, {%8,%9}, {%0,%1,%2,%3};\n"
        : "+f"(d[0]), "+f"(d[1]), "+f"(d[2]), "+f"(d[3])
        : "r"(a[0]), "r"(a[1]), "r"(a[2]), "r"(a[3]), "r"(b[0]), "r"(b[1]));
}

// ---------------- conversion kernels ----------------
__global__ void convert_x_kernel(const float* __restrict__ X)
{
    const int i = blockIdx.x * 256 + threadIdx.x;
    if (i < M_ROWS * K_DIM) X16[i] = __float2bfloat16(X[i]);
    if (i < M_ROWS) g_ccnt[i] = 0;
}

__global__ void convert_w_kernel(const float* __restrict__ W)
{
    const int row  = blockIdx.x * 8 + (threadIdx.x >> 5);
    const int lane = threadIdx.x & 31;
    const float* w = W + (size_t)row * K_DIM;
    float s = 0.0f;
    for (int i = lane; i < K_DIM; i += 32) {
        const float v = w[i];
        s = fmaf(v, v, s);
        W16[(size_t)row * K_DIM + i] = __float2bfloat16(v);
    }
#pragma unroll
    for (int o = 16; o; o >>= 1) s += __shfl_xor_sync(0xFFFFFFFFu, s, o);
    if (lane == 0) g_invnorm[row] = rsqrtf(s);
}

// ---------------- zero the encoded output region ----------------
__global__ void zero_kernel(float4* __restrict__ p, int n4)
{
    const float4 z = make_float4(0.f, 0.f, 0.f, 0.f);
    for (int i = blockIdx.x * blockDim.x + threadIdx.x; i < n4;
         i += gridDim.x * blockDim.x)
        p[i] = z;
}

// ---------------- encoder GEMM (bf16 mma.sync), candidate-append epilogue ------
__device__ __forceinline__ void ldtile16(int m0, int n0, int kt,
                                         uint32_t* As, uint32_t* Bs, int t)
{
#pragma unroll
    for (int it = 0; it < 2; it++) {
        const int g = t + it * 256;          // 0..511
        const int r = g >> 2;                // 0..127
        const int c = g & 3;                 // 16B granule
        CP_ASYNC16(cvta_shared(As + r * TS + c * 4),
                   X16 + (size_t)(m0 + r) * K_DIM + kt + c * 8);
        CP_ASYNC16(cvta_shared(Bs + r * TS + c * 4),
                   W16 + (size_t)(n0 + r) * K_DIM + kt + c * 8);
    }
}

__device__ __forceinline__ void cand_append(int row, int col, float v)
{
    if (v > THRESH) {
        const int q = atomicAdd(&g_ccnt[row], 1);
        if (q < CAP) {
            g_cidx[(size_t)row * CAP + q] = col;
            g_cval[(size_t)row * CAP + q] = v;
        }
    }
}

__global__ void __launch_bounds__(256, 2) encode_gemm(const float* __restrict__ bias)
{
    __shared__ uint32_t As[2][128 * TS];
    __shared__ uint32_t Bs[2][128 * TS];

    const int t    = threadIdx.x;
    const int lane = t & 31;
    const int wid  = t >> 5;
    const int m0   = blockIdx.x * 128;
    const int n0   = blockIdx.y * 128;
    const int wm   = (wid & 1) * 64;
    const int wn   = (wid >> 1) * 32;
    const int fg   = lane >> 2;
    const int fc   = lane & 3;

    float acc[4][4][4];
#pragma unroll
    for (int i = 0; i < 4; i++)
#pragma unroll
        for (int j = 0; j < 4; j++)
#pragma unroll
            for (int r = 0; r < 4; r++) acc[i][j][r] = 0.0f;

    ldtile16(m0, n0, 0, As[0], Bs[0], t);
    CP_COMMIT();

    for (int kt = 0; kt < NKTILE; kt++) {
        const int s = kt & 1;
        if (kt + 1 < NKTILE) {
            ldtile16(m0, n0, (kt + 1) * 32, As[s ^ 1], Bs[s ^ 1], t);
            CP_COMMIT();
            CP_WAIT1();
        } else {
            CP_WAIT0();
        }
        __syncthreads();

        const uint32_t* Au = As[s];
        const uint32_t* Bu = Bs[s];
#pragma unroll
        for (int ks = 0; ks < BKW; ks += 8) {
            uint32_t a[4][4], b[4][2];
#pragma unroll
            for (int mi = 0; mi < 4; mi++) {
                const uint32_t* ap = Au + (wm + mi * 16) * TS + ks;
                a[mi][0] = ap[fg * TS + fc];
                a[mi][1] = ap[(fg + 8) * TS + fc];
                a[mi][2] = ap[fg * TS + fc + 4];
                a[mi][3] = ap[(fg + 8) * TS + fc + 4];
            }
#pragma unroll
            for (int nj = 0; nj < 4; nj++) {
                const uint32_t* bp = Bu + (wn + nj * 8 + fg) * TS + ks;
                b[nj][0] = bp[fc];
                b[nj][1] = bp[fc + 4];
            }
#pragma unroll
            for (int mi = 0; mi < 4; mi++)
#pragma unroll
                for (int nj = 0; nj < 4; nj++)
                    mma_bf16(acc[mi][nj], a[mi], b[nj]);
        }
        __syncthreads();
    }

    // epilogue: threshold + append candidates (no dense store)
#pragma unroll
    for (int nj = 0; nj < 4; nj++) {
        const int col = n0 + wn + nj * 8 + fc * 2;
        const float b0 = bias[col], b1 = bias[col + 1];
#pragma unroll
        for (int mi = 0; mi < 4; mi++) {
            const int row = m0 + wm + mi * 16 + fg;
            cand_append(row,     col,     acc[mi][nj][0] + b0);
            cand_append(row,     col + 1, acc[mi][nj][1] + b1);
            cand_append(row + 8, col,     acc[mi][nj][2] + b0);
            cand_append(row + 8, col + 1, acc[mi][nj][3] + b1);
        }
    }
}

// ---------------- top-k fixup ----------------
__device__ __forceinline__ unsigned int f2u(float f)
{
    unsigned int b = __float_as_uint(f);
    return (b & 0x80000000u) ? ~b : (b | 0x80000000u);
}

// exact key of k-th largest over arr[0..n), 256-thread block collective
__device__ unsigned int radix_key(const float* arr, int n, int k,
                                  unsigned int* hist, unsigned int* cbuf,
                                  unsigned int* prefixSh, unsigned int* kSh, int t)
{
    if (t == 0) { *prefixSh = 0; *kSh = (unsigned int)k; }
    __syncthreads();
    for (int pass = 3; pass >= 0; --pass) {
        const int shift = pass * 8;
        hist[t] = 0;
        __syncthreads();
        const unsigned int prefix = *prefixSh;
        for (int i = t; i < n; i += 256) {
            const unsigned int u = f2u(arr[i]);
            bool cand = (pass == 3) || ((u >> (shift + 8)) == (prefix >> (shift + 8)));
            if (cand) atomicAdd(&hist[(u >> shift) & 0xFFu], 1u);
        }
        __syncthreads();
        cbuf[t] = hist[t];
        __syncthreads();
        for (int off = 1; off < 256; off <<= 1) {
            unsigned int v   = cbuf[t];
            unsigned int add = (t + off < 256) ? cbuf[t + off] : 0u;
            __syncthreads();
            cbuf[t] = v + add;
            __syncthreads();
        }
        const unsigned int kcur  = *kSh;
        const unsigned int here  = cbuf[t];
        const unsigned int above = (t < 255) ? cbuf[t + 1] : 0u;
        __syncthreads();
        if (here >= kcur && above < kcur) {
            *prefixSh = prefix | ((unsigned int)t << shift);
            *kSh = kcur - above;
        }
        __syncthreads();
    }
    return *prefixSh;
}

__global__ void __launch_bounds__(256) fixup_kernel(
    const float* __restrict__ X, const float* __restrict__ W,
    const float* __restrict__ bias, float* __restrict__ enc)
{
    const int row = blockIdx.x;
    float* p = enc + (size_t)row * N_HID;
    const int t = threadIdx.x;

    __shared__ float xrow[K_DIM];
    __shared__ float cval_s[CAP];
    __shared__ unsigned int hist[256], cbuf[256];
    __shared__ unsigned int prefixSh, kSh;
    __shared__ int nsel2, nfin;
    __shared__ int   sel_i[MAX_CAND];
    __shared__ float sel_v[MAX_CAND];

    for (int i = t; i < K_DIM; i += 256) xrow[i] = X[(size_t)row * K_DIM + i];
    if (t == 0) { nsel2 = 0; nfin = 0; }
    __syncthreads();

    const int cnt = g_ccnt[row];
    if (cnt >= RANK_SEL && cnt <= CAP) {
        for (int i = t; i < cnt; i += 256) cval_s[i] = g_cval[(size_t)row * CAP + i];
        __syncthreads();
        const unsigned int key = radix_key(cval_s, cnt, RANK_SEL,
                                           hist, cbuf, &prefixSh, &kSh, t);
        for (int i = t; i < cnt; i += 256) {
            if (f2u(cval_s[i]) >= key) {
                const int q = atomicAdd(&nsel2, 1);
                if (q < MAX_CAND) sel_i[q] = g_cidx[(size_t)row * CAP + i];
            }
        }
    } else {
        // fallback (statistically never taken): exact full-row recompute
        for (int n = t; n < N_HID; n += 256) {
            const float* wr = W + (size_t)n * K_DIM;
            float s = 0.0f;
            for (int k2 = 0; k2 < K_DIM; k2++) s = fmaf(xrow[k2], wr[k2], s);
            p[n] = s + bias[n];
        }
        __syncthreads();
        const unsigned int key = radix_key(p, N_HID, RANK_SEL,
                                           hist, cbuf, &prefixSh, &kSh, t);
        for (int i = t; i < N_HID; i += 256) {
            if (f2u(p[i]) >= key) {
                const int q = atomicAdd(&nsel2, 1);
                if (q < MAX_CAND) sel_i[q] = i;
            }
        }
        __syncthreads();
        float4 z4 = make_float4(0.f, 0.f, 0.f, 0.f);
        for (int i = t; i < N_HID / 4; i += 256) ((float4*)p)[i] = z4;  // re-zero
    }
    __syncthreads();
    const int nc = (nsel2 < MAX_CAND) ? nsel2 : MAX_CAND;

    // exact fp32 dot products for selected candidates (one warp per candidate)
    const int lane = t & 31, w = t >> 5;
    for (int i = w; i < nc; i += 8) {
        const float* wr = W + (size_t)sel_i[i] * K_DIM;
        float s = 0.0f;
#pragma unroll 4
        for (int j = lane; j < K_DIM; j += 32) s = fmaf(xrow[j], wr[j], s);
#pragma unroll
        for (int o = 16; o; o >>= 1) s += __shfl_xor_sync(0xFFFFFFFFu, s, o);
        if (lane == 0) sel_v[i] = s + bias[sel_i[i]];
    }
    __syncthreads();

    // exact rank; keep if fewer than K_SPARSE strictly greater (keeps ties)
    if (t < nc) {
        const float v = sel_v[t];
        int cg = 0;
        for (int j = 0; j < nc; j++) cg += (sel_v[j] > v);
        if (cg < K_SPARSE) {
            p[sel_i[t]] = v;
            const int q = atomicAdd(&nfin, 1);
            if (q < MAX_ACT) {
                g_idx[row * MAX_ACT + q] = sel_i[t];
                g_val[row * MAX_ACT + q] = v;
            }
        }
    }
    __syncthreads();
    if (t == 0) g_cnt[row] = (nfin > MAX_ACT) ? MAX_ACT : nfin;
}

// ---------------- sparse decoder ----------------
__global__ void __launch_bounds__(256) decode_kernel(
    const float* __restrict__ W, float* __restrict__ dec)
{
    const int row = blockIdx.x;
    const int t = threadIdx.x;

    __shared__ float coef[MAX_ACT];
    __shared__ int   jrow[MAX_ACT];

    const int c = g_cnt[row];
    if (t < MAX_ACT && t < c) {
        const int j = g_idx[row * MAX_ACT + t];
        jrow[t] = j;
        coef[t] = g_val[row * MAX_ACT + t] * g_invnorm[j];
    }
    __syncthreads();

    float a0 = 0.0f, a1 = 0.0f, a2 = 0.0f;
    for (int j = 0; j < c; ++j) {
        const float* w = W + (size_t)jrow[j] * K_DIM;
        const float cf = coef[j];
        a0 = fmaf(cf, w[t],       a0);
        a1 = fmaf(cf, w[t + 256], a1);
        a2 = fmaf(cf, w[t + 512], a2);
    }
    float* o = dec + (size_t)row * K_DIM;
    o[t] = a0; o[t + 256] = a1; o[t + 512] = a2;
}

// ---------------- launch ----------------
extern "C" void kernel_launch(void* const* d_in, const int* in_sizes, int n_in,
                              void* d_out, int out_size)
{
    const float* x = (const float*)d_in[0];
    const float* W = (const float*)d_in[1];
    const float* b = (const float*)d_in[2];
    float* out = (float*)d_out;

    float* dec = out;                               // [4096, 768]
    float* enc = out + (size_t)M_ROWS * K_DIM;      // [4096, 16384]

    convert_x_kernel<<<(M_ROWS * K_DIM + 255) / 256, 256>>>(x);
    convert_w_kernel<<<N_HID / 8, 256>>>(W);
    zero_kernel<<<4096, 256>>>((float4*)enc, M_ROWS * N_HID / 4);

    dim3 ggrid(M_ROWS / 128, N_HID / 128);          // x fast: consecutive CTAs share B tile
    encode_gemm<<<ggrid, 256>>>(b);
    fixup_kernel<<<M_ROWS, 256>>>(x, W, b, enc);
    decode_kernel<<<M_ROWS, 256>>>(W, dec);
}

// round 7
// speedup vs baseline: 3.9846x; 1.0293x over previous
#include <cuda_runtime.h>
#include <cuda_bf16.h>
#include <cstdint>

#define M_ROWS 4096
#define N_HID  16384
#define K_DIM  768
#define K_SPARSE 32
#define MAX_ACT  64
#define MAX_CAND 96
#define RANK_SEL 64
#define CAP      1024
#define THRESH   2.0f

// GEMM tiling: 128x128 CTA tile, BK=32 bf16 (16 words), double-buffered
#define BKW 16                 // words (4B) per smem row
#define TS  20                 // padded word stride (conflict-free for ldmatrix)
#define NKTILE (K_DIM / 32)    // 24

// ---------------- device scratch ----------------
__device__ __nv_bfloat16 X16[M_ROWS * K_DIM];
__device__ __nv_bfloat16 W16[N_HID * K_DIM];
__device__ int   g_ccnt[M_ROWS];
__device__ int   g_cidx[(size_t)M_ROWS * CAP];
__device__ float g_cval[(size_t)M_ROWS * CAP];
__device__ int   g_cnt[M_ROWS];
__device__ int   g_idx[M_ROWS * MAX_ACT];
__device__ float g_val[M_ROWS * MAX_ACT];
__device__ float g_invnorm[N_HID];

// ---------------- PTX helpers ----------------
__device__ __forceinline__ uint32_t cvta_shared(const void* p) {
    return (uint32_t)__cvta_generic_to_shared(p);
}
#define CP_ASYNC16(dst, src) \
    asm volatile("cp.async.cg.shared.global [%0], [%1], 16;\n" :: "r"(dst), "l"(src))
#define CP_COMMIT() asm volatile("cp.async.commit_group;\n" ::: "memory")
#define CP_WAIT1()  asm volatile("cp.async.wait_group 1;\n" ::: "memory")
#define CP_WAIT0()  asm volatile("cp.async.wait_group 0;\n" ::: "memory")

#define LDSM_X4(r, addr) \
    asm volatile("ldmatrix.sync.aligned.m8n8.x4.shared.b16 {%0,%1,%2,%3}, [%4];" \
        : "=r"((r)[0]), "=r"((r)[1]), "=r"((r)[2]), "=r"((r)[3]) : "r"(addr))

__device__ __forceinline__ void mma_bf16(float* d, const uint32_t* a, const uint32_t* b)
{
    asm volatile(
        "mma.sync.aligned.m16n8k16.row.col.f32.bf16.bf16.f32 "
        "{%0,%1,%2,%3}, {%4,%5,%6,%7}, {%8,%9}, {%0,%1,%2,%3};\n"
        : "+f"(d[0]), "+f"(d[1]), "+f"(d[2]), "+f"(d[3])
        : "r"(a[0]), "r"(a[1]), "r"(a[2]), "r"(a[3]), "r"(b[0]), "r"(b[1]));
}

// ---------------- conversion kernels ----------------
__global__ void convert_x_kernel(const float* __restrict__ X)
{
    const int i = blockIdx.x * 256 + threadIdx.x;
    if (i < M_ROWS * K_DIM) X16[i] = __float2bfloat16(X[i]);
    if (i < M_ROWS) g_ccnt[i] = 0;
}

__global__ void convert_w_kernel(const float* __restrict__ W)
{
    const int row  = blockIdx.x * 8 + (threadIdx.x >> 5);
    const int lane = threadIdx.x & 31;
    const float* w = W + (size_t)row * K_DIM;
    float s = 0.0f;
    for (int i = lane; i < K_DIM; i += 32) {
        const float v = w[i];
        s = fmaf(v, v, s);
        W16[(size_t)row * K_DIM + i] = __float2bfloat16(v);
    }
#pragma unroll
    for (int o = 16; o; o >>= 1) s += __shfl_xor_sync(0xFFFFFFFFu, s, o);
    if (lane == 0) g_invnorm[row] = rsqrtf(s);
}

// ---------------- zero the encoded output region ----------------
__global__ void zero_kernel(float4* __restrict__ p, int n4)
{
    const float4 z = make_float4(0.f, 0.f, 0.f, 0.f);
    for (int i = blockIdx.x * blockDim.x + threadIdx.x; i < n4;
         i += gridDim.x * blockDim.x)
        p[i] = z;
}

// ---------------- encoder GEMM (bf16 mma.sync + ldmatrix) ----------------------
__device__ __forceinline__ void ldtile16(int m0, int n0, int kt,
                                         uint32_t* As, uint32_t* Bs, int t)
{
#pragma unroll
    for (int it = 0; it < 2; it++) {
        const int g = t + it * 256;          // 0..511
        const int r = g >> 2;                // 0..127
        const int c = g & 3;                 // 16B granule
        CP_ASYNC16(cvta_shared(As + r * TS + c * 4),
                   X16 + (size_t)(m0 + r) * K_DIM + kt + c * 8);
        CP_ASYNC16(cvta_shared(Bs + r * TS + c * 4),
                   W16 + (size_t)(n0 + r) * K_DIM + kt + c * 8);
    }
}

__device__ __forceinline__ void cand_append(int row, int col, float v)
{
    if (v > THRESH) {
        const int q = atomicAdd(&g_ccnt[row], 1);
        if (q < CAP) {
            g_cidx[(size_t)row * CAP + q] = col;
            g_cval[(size_t)row * CAP + q] = v;
        }
    }
}

__global__ void __launch_bounds__(256, 2) encode_gemm(const float* __restrict__ bias)
{
    __shared__ uint32_t As[2][128 * TS];
    __shared__ uint32_t Bs[2][128 * TS];

    const int t    = threadIdx.x;
    const int lane = t & 31;
    const int wid  = t >> 5;
    const int m0   = blockIdx.x * 128;
    const int n0   = blockIdx.y * 128;
    const int wm   = (wid & 1) * 64;
    const int wn   = (wid >> 1) * 32;
    const int fg   = lane >> 2;
    const int fc   = lane & 3;

    // per-thread ldmatrix address offsets (bytes) within a stage
    // A 16x16 tile: M0 rows0-7/klo, M1 rows8-15/klo, M2 rows0-7/khi, M3 rows8-15/khi
    const uint32_t aoff = ((wm + (lane & 15)) * TS + ((lane >> 4) << 2)) * 4;
    // B nj-pair: M0 nj0/klo, M1 nj0/khi, M2 nj1/klo, M3 nj1/khi
    const uint32_t boff = ((wn + (lane & 7) + ((lane >> 4) << 3)) * TS
                           + (((lane >> 3) & 1) << 2)) * 4;

    float acc[4][4][4];
#pragma unroll
    for (int i = 0; i < 4; i++)
#pragma unroll
        for (int j = 0; j < 4; j++)
#pragma unroll
            for (int r = 0; r < 4; r++) acc[i][j][r] = 0.0f;

    ldtile16(m0, n0, 0, As[0], Bs[0], t);
    CP_COMMIT();

    for (int kt = 0; kt < NKTILE; kt++) {
        const int s = kt & 1;
        if (kt + 1 < NKTILE) {
            ldtile16(m0, n0, (kt + 1) * 32, As[s ^ 1], Bs[s ^ 1], t);
            CP_COMMIT();
            CP_WAIT1();
        } else {
            CP_WAIT0();
        }
        __syncthreads();

        const uint32_t Ab = cvta_shared(As[s]);
        const uint32_t Bb = cvta_shared(Bs[s]);
#pragma unroll
        for (int ks = 0; ks < BKW; ks += 8) {
            uint32_t a[4][4], b[2][4];
#pragma unroll
            for (int mi = 0; mi < 4; mi++)
                LDSM_X4(a[mi], Ab + aoff + (mi * 16 * TS + ks) * 4);
#pragma unroll
            for (int njp = 0; njp < 2; njp++)
                LDSM_X4(b[njp], Bb + boff + (njp * 16 * TS + ks) * 4);
#pragma unroll
            for (int mi = 0; mi < 4; mi++)
#pragma unroll
                for (int nj = 0; nj < 4; nj++)
                    mma_bf16(acc[mi][nj], a[mi], &b[nj >> 1][(nj & 1) * 2]);
        }
        __syncthreads();
    }

    // epilogue: threshold + append candidates (no dense store)
#pragma unroll
    for (int nj = 0; nj < 4; nj++) {
        const int col = n0 + wn + nj * 8 + fc * 2;
        const float b0 = bias[col], b1 = bias[col + 1];
#pragma unroll
        for (int mi = 0; mi < 4; mi++) {
            const int row = m0 + wm + mi * 16 + fg;
            cand_append(row,     col,     acc[mi][nj][0] + b0);
            cand_append(row,     col + 1, acc[mi][nj][1] + b1);
            cand_append(row + 8, col,     acc[mi][nj][2] + b0);
            cand_append(row + 8, col + 1, acc[mi][nj][3] + b1);
        }
    }
}

// ---------------- top-k fixup ----------------
__device__ __forceinline__ unsigned int f2u(float f)
{
    unsigned int b = __float_as_uint(f);
    return (b & 0x80000000u) ? ~b : (b | 0x80000000u);
}

// exact key of k-th largest over arr[0..n), 256-thread block collective
__device__ unsigned int radix_key(const float* arr, int n, int k,
                                  unsigned int* hist, unsigned int* cbuf,
                                  unsigned int* prefixSh, unsigned int* kSh, int t)
{
    if (t == 0) { *prefixSh = 0; *kSh = (unsigned int)k; }
    __syncthreads();
    for (int pass = 3; pass >= 0; --pass) {
        const int shift = pass * 8;
        hist[t] = 0;
        __syncthreads();
        const unsigned int prefix = *prefixSh;
        for (int i = t; i < n; i += 256) {
            const unsigned int u = f2u(arr[i]);
            bool cand = (pass == 3) || ((u >> (shift + 8)) == (prefix >> (shift + 8)));
            if (cand) atomicAdd(&hist[(u >> shift) & 0xFFu], 1u);
        }
        __syncthreads();
        cbuf[t] = hist[t];
        __syncthreads();
        for (int off = 1; off < 256; off <<= 1) {
            unsigned int v   = cbuf[t];
            unsigned int add = (t + off < 256) ? cbuf[t + off] : 0u;
            __syncthreads();
            cbuf[t] = v + add;
            __syncthreads();
        }
        const unsigned int kcur  = *kSh;
        const unsigned int here  = cbuf[t];
        const unsigned int above = (t < 255) ? cbuf[t + 1] : 0u;
        __syncthreads();
        if (here >= kcur && above < kcur) {
            *prefixSh = prefix | ((unsigned int)t << shift);
            *kSh = kcur - above;
        }
        __syncthreads();
    }
    return *prefixSh;
}

__global__ void __launch_bounds__(256) fixup_kernel(
    const float* __restrict__ X, const float* __restrict__ W,
    const float* __restrict__ bias, float* __restrict__ enc)
{
    const int row = blockIdx.x;
    float* p = enc + (size_t)row * N_HID;
    const int t = threadIdx.x;

    __shared__ float xrow[K_DIM];
    __shared__ float cval_s[CAP];
    __shared__ unsigned int hist[256], cbuf[256];
    __shared__ unsigned int prefixSh, kSh;
    __shared__ int nsel2, nfin;
    __shared__ int   sel_i[MAX_CAND];
    __shared__ float sel_v[MAX_CAND];

    for (int i = t; i < K_DIM; i += 256) xrow[i] = X[(size_t)row * K_DIM + i];
    if (t == 0) { nsel2 = 0; nfin = 0; }
    __syncthreads();

    const int cnt = g_ccnt[row];
    if (cnt >= RANK_SEL && cnt <= CAP) {
        for (int i = t; i < cnt; i += 256) cval_s[i] = g_cval[(size_t)row * CAP + i];
        __syncthreads();
        const unsigned int key = radix_key(cval_s, cnt, RANK_SEL,
                                           hist, cbuf, &prefixSh, &kSh, t);
        for (int i = t; i < cnt; i += 256) {
            if (f2u(cval_s[i]) >= key) {
                const int q = atomicAdd(&nsel2, 1);
                if (q < MAX_CAND) sel_i[q] = g_cidx[(size_t)row * CAP + i];
            }
        }
    } else {
        // fallback (statistically never taken): exact full-row recompute
        for (int n = t; n < N_HID; n += 256) {
            const float* wr = W + (size_t)n * K_DIM;
            float s = 0.0f;
            for (int k2 = 0; k2 < K_DIM; k2++) s = fmaf(xrow[k2], wr[k2], s);
            p[n] = s + bias[n];
        }
        __syncthreads();
        const unsigned int key = radix_key(p, N_HID, RANK_SEL,
                                           hist, cbuf, &prefixSh, &kSh, t);
        for (int i = t; i < N_HID; i += 256) {
            if (f2u(p[i]) >= key) {
                const int q = atomicAdd(&nsel2, 1);
                if (q < MAX_CAND) sel_i[q] = i;
            }
        }
        __syncthreads();
        float4 z4 = make_float4(0.f, 0.f, 0.f, 0.f);
        for (int i = t; i < N_HID / 4; i += 256) ((float4*)p)[i] = z4;  // re-zero
    }
    __syncthreads();
    const int nc = (nsel2 < MAX_CAND) ? nsel2 : MAX_CAND;

    // exact fp32 dot products for selected candidates (one warp per candidate)
    const int lane = t & 31, w = t >> 5;
    for (int i = w; i < nc; i += 8) {
        const float* wr = W + (size_t)sel_i[i] * K_DIM;
        float s = 0.0f;
#pragma unroll 4
        for (int j = lane; j < K_DIM; j += 32) s = fmaf(xrow[j], wr[j], s);
#pragma unroll
        for (int o = 16; o; o >>= 1) s += __shfl_xor_sync(0xFFFFFFFFu, s, o);
        if (lane == 0) sel_v[i] = s + bias[sel_i[i]];
    }
    __syncthreads();

    // exact rank; keep if fewer than K_SPARSE strictly greater (keeps ties)
    if (t < nc) {
        const float v = sel_v[t];
        int cg = 0;
        for (int j = 0; j < nc; j++) cg += (sel_v[j] > v);
        if (cg < K_SPARSE) {
            p[sel_i[t]] = v;
            const int q = atomicAdd(&nfin, 1);
            if (q < MAX_ACT) {
                g_idx[row * MAX_ACT + q] = sel_i[t];
                g_val[row * MAX_ACT + q] = v;
            }
        }
    }
    __syncthreads();
    if (t == 0) g_cnt[row] = (nfin > MAX_ACT) ? MAX_ACT : nfin;
}

// ---------------- sparse decoder ----------------
__global__ void __launch_bounds__(256) decode_kernel(
    const float* __restrict__ W, float* __restrict__ dec)
{
    const int row = blockIdx.x;
    const int t = threadIdx.x;

    __shared__ float coef[MAX_ACT];
    __shared__ int   jrow[MAX_ACT];

    const int c = g_cnt[row];
    if (t < MAX_ACT && t < c) {
        const int j = g_idx[row * MAX_ACT + t];
        jrow[t] = j;
        coef[t] = g_val[row * MAX_ACT + t] * g_invnorm[j];
    }
    __syncthreads();

    float a0 = 0.0f, a1 = 0.0f, a2 = 0.0f;
    for (int j = 0; j < c; ++j) {
        const float* w = W + (size_t)jrow[j] * K_DIM;
        const float cf = coef[j];
        a0 = fmaf(cf, w[t],       a0);
        a1 = fmaf(cf, w[t + 256], a1);
        a2 = fmaf(cf, w[t + 512], a2);
    }
    float* o = dec + (size_t)row * K_DIM;
    o[t] = a0; o[t + 256] = a1; o[t + 512] = a2;
}

// ---------------- launch ----------------
extern "C" void kernel_launch(void* const* d_in, const int* in_sizes, int n_in,
                              void* d_out, int out_size)
{
    const float* x = (const float*)d_in[0];
    const float* W = (const float*)d_in[1];
    const float* b = (const float*)d_in[2];
    float* out = (float*)d_out;

    float* dec = out;                               // [4096, 768]
    float* enc = out + (size_t)M_ROWS * K_DIM;      // [4096, 16384]

    convert_x_kernel<<<(M_ROWS * K_DIM + 255) / 256, 256>>>(x);
    convert_w_kernel<<<N_HID / 8, 256>>>(W);
    zero_kernel<<<4096, 256>>>((float4*)enc, M_ROWS * N_HID / 4);

    dim3 ggrid(M_ROWS / 128, N_HID / 128);          // x fast: consecutive CTAs share B tile
    encode_gemm<<<ggrid, 256>>>(b);
    fixup_kernel<<<M_ROWS, 256>>>(x, W, b, enc);
    decode_kernel<<<M_ROWS, 256>>>(W, dec);
}

// round 8
// speedup vs baseline: 4.2121x; 1.0571x over previous
#include <cuda_runtime.h>
#include <cuda_bf16.h>
#include <cstdint>

#define M_ROWS 4096
#define N_HID  16384
#define K_DIM  768
#define K_SPARSE 32
#define MAX_ACT  64
#define MAX_CAND 96
#define RANK_SEL 64
#define CAP      1024
#define THRESH   2.0f

// GEMM tiling: 128x128 CTA tile, BK=32 bf16 (16 words), 3-stage pipeline
#define BKW 16                 // words (4B) per smem row
#define TS  20                 // padded word stride (conflict-free for ldmatrix)
#define NKTILE (K_DIM / 32)    // 24
#define STG_WORDS (128 * TS)   // words per A (or B) stage
#define STAGE_TOT (2 * STG_WORDS)  // A+B words per stage
#define NSTAGE 3

// ---------------- device scratch ----------------
__device__ __nv_bfloat16 X16[M_ROWS * K_DIM];
__device__ __nv_bfloat16 W16[N_HID * K_DIM];
__device__ int   g_ccnt[M_ROWS];
__device__ int   g_cidx[(size_t)M_ROWS * CAP];
__device__ float g_cval[(size_t)M_ROWS * CAP];
__device__ int   g_cnt[M_ROWS];
__device__ int   g_idx[M_ROWS * MAX_ACT];
__device__ float g_val[M_ROWS * MAX_ACT];
__device__ float g_invnorm[N_HID];

// ---------------- PTX helpers ----------------
__device__ __forceinline__ uint32_t cvta_shared(const void* p) {
    return (uint32_t)__cvta_generic_to_shared(p);
}
#define CP_ASYNC16(dst, src) \
    asm volatile("cp.async.cg.shared.global [%0], [%1], 16;\n" :: "r"(dst), "l"(src))
#define CP_COMMIT() asm volatile("cp.async.commit_group;\n" ::: "memory")
#define CP_WAIT1()  asm volatile("cp.async.wait_group 1;\n" ::: "memory")

#define LDSM_X4(r, addr) \
    asm volatile("ldmatrix.sync.aligned.m8n8.x4.shared.b16 {%0,%1,%2,%3}, [%4];" \
        : "=r"((r)[0]), "=r"((r)[1]), "=r"((r)[2]), "=r"((r)[3]) : "r"(addr))

__device__ __forceinline__ void mma_bf16(float* d, const uint32_t* a, const uint32_t* b)
{
    asm volatile(
        "mma.sync.aligned.m16n8k16.row.col.f32.bf16.bf16.f32 "
        "{%0,%1,%2,%3}, {%4,%5,%6,%7}, {%8,%9}, {%0,%1,%2,%3};\n"
        : "+f"(d[0]), "+f"(d[1]), "+f"(d[2]), "+f"(d[3])
        : "r"(a[0]), "r"(a[1]), "r"(a[2]), "r"(a[3]), "r"(b[0]), "r"(b[1]));
}

// ---------------- conversion kernels ----------------
__global__ void convert_x_kernel(const float* __restrict__ X)
{
    const int i = blockIdx.x * 256 + threadIdx.x;
    if (i < M_ROWS * K_DIM) X16[i] = __float2bfloat16(X[i]);
    if (i < M_ROWS) g_ccnt[i] = 0;
}

__global__ void convert_w_kernel(const float* __restrict__ W)
{
    const int row  = blockIdx.x * 8 + (threadIdx.x >> 5);
    const int lane = threadIdx.x & 31;
    const float* w = W + (size_t)row * K_DIM;
    float s = 0.0f;
    for (int i = lane; i < K_DIM; i += 32) {
        const float v = w[i];
        s = fmaf(v, v, s);
        W16[(size_t)row * K_DIM + i] = __float2bfloat16(v);
    }
#pragma unroll
    for (int o = 16; o; o >>= 1) s += __shfl_xor_sync(0xFFFFFFFFu, s, o);
    if (lane == 0) g_invnorm[row] = rsqrtf(s);
}

// ---------------- zero the encoded output region ----------------
__global__ void zero_kernel(float4* __restrict__ p, int n4)
{
    const float4 z = make_float4(0.f, 0.f, 0.f, 0.f);
    for (int i = blockIdx.x * blockDim.x + threadIdx.x; i < n4;
         i += gridDim.x * blockDim.x)
        p[i] = z;
}

// ---------------- encoder GEMM (bf16 mma.sync + ldmatrix, 3-stage) -------------
__device__ __forceinline__ void ldtile16(int m0, int n0, int kt,
                                         uint32_t* As, uint32_t* Bs, int t)
{
#pragma unroll
    for (int it = 0; it < 2; it++) {
        const int g = t + it * 256;          // 0..511
        const int r = g >> 2;                // 0..127
        const int c = g & 3;                 // 16B granule
        CP_ASYNC16(cvta_shared(As + r * TS + c * 4),
                   X16 + (size_t)(m0 + r) * K_DIM + kt + c * 8);
        CP_ASYNC16(cvta_shared(Bs + r * TS + c * 4),
                   W16 + (size_t)(n0 + r) * K_DIM + kt + c * 8);
    }
}

__device__ __forceinline__ void cand_append(int row, int col, float v)
{
    if (v > THRESH) {
        const int q = atomicAdd(&g_ccnt[row], 1);
        if (q < CAP) {
            g_cidx[(size_t)row * CAP + q] = col;
            g_cval[(size_t)row * CAP + q] = v;
        }
    }
}

__global__ void __launch_bounds__(256, 2) encode_gemm(const float* __restrict__ bias)
{
    extern __shared__ uint32_t smem[];   // NSTAGE * STAGE_TOT words

    const int t    = threadIdx.x;
    const int lane = t & 31;
    const int wid  = t >> 5;
    const int m0   = blockIdx.x * 128;
    const int n0   = blockIdx.y * 128;
    const int wm   = (wid & 1) * 64;
    const int wn   = (wid >> 1) * 32;
    const int fg   = lane >> 2;
    const int fc   = lane & 3;

    // per-thread ldmatrix address offsets (bytes) within a stage
    const uint32_t aoff = ((wm + (lane & 15)) * TS + ((lane >> 4) << 2)) * 4;
    const uint32_t boff = ((wn + (lane & 7) + ((lane >> 4) << 3)) * TS
                           + (((lane >> 3) & 1) << 2)) * 4;

    float acc[4][4][4];
#pragma unroll
    for (int i = 0; i < 4; i++)
#pragma unroll
        for (int j = 0; j < 4; j++)
#pragma unroll
            for (int r = 0; r < 4; r++) acc[i][j][r] = 0.0f;

    // prologue: stages 0 and 1 in flight
    ldtile16(m0, n0, 0,  smem,             smem + STG_WORDS,             t);
    CP_COMMIT();
    ldtile16(m0, n0, 32, smem + STAGE_TOT, smem + STAGE_TOT + STG_WORDS, t);
    CP_COMMIT();

    int stage = 0, nstage = 2;
    for (int kt = 0; kt < NKTILE; kt++) {
        CP_WAIT1();                // tile kt's loads complete (<=1 newer pending)
        __syncthreads();           // all warps past reads of the stage being refilled

        if (kt + 2 < NKTILE) {
            uint32_t* sb = smem + nstage * STAGE_TOT;
            ldtile16(m0, n0, (kt + 2) * 32, sb, sb + STG_WORDS, t);
        }
        CP_COMMIT();               // keep group count consistent (may be empty)

        const uint32_t Ab = cvta_shared(smem + stage * STAGE_TOT);
        const uint32_t Bb = Ab + STG_WORDS * 4;
#pragma unroll
        for (int ks = 0; ks < BKW; ks += 8) {
            uint32_t a[4][4], b[2][4];
#pragma unroll
            for (int mi = 0; mi < 4; mi++)
                LDSM_X4(a[mi], Ab + aoff + (mi * 16 * TS + ks) * 4);
#pragma unroll
            for (int njp = 0; njp < 2; njp++)
                LDSM_X4(b[njp], Bb + boff + (njp * 16 * TS + ks) * 4);
#pragma unroll
            for (int mi = 0; mi < 4; mi++)
#pragma unroll
                for (int nj = 0; nj < 4; nj++)
                    mma_bf16(acc[mi][nj], a[mi], &b[nj >> 1][(nj & 1) * 2]);
        }

        stage  = (stage  + 1 == NSTAGE) ? 0 : stage + 1;
        nstage = (nstage + 1 == NSTAGE) ? 0 : nstage + 1;
    }

    // epilogue: threshold + append candidates (no dense store)
#pragma unroll
    for (int nj = 0; nj < 4; nj++) {
        const int col = n0 + wn + nj * 8 + fc * 2;
        const float b0 = bias[col], b1 = bias[col + 1];
#pragma unroll
        for (int mi = 0; mi < 4; mi++) {
            const int row = m0 + wm + mi * 16 + fg;
            cand_append(row,     col,     acc[mi][nj][0] + b0);
            cand_append(row,     col + 1, acc[mi][nj][1] + b1);
            cand_append(row + 8, col,     acc[mi][nj][2] + b0);
            cand_append(row + 8, col + 1, acc[mi][nj][3] + b1);
        }
    }
}

// ---------------- top-k fixup ----------------
__device__ __forceinline__ unsigned int f2u(float f)
{
    unsigned int b = __float_as_uint(f);
    return (b & 0x80000000u) ? ~b : (b | 0x80000000u);
}

// exact key of k-th largest over arr[0..n), 256-thread block collective
__device__ unsigned int radix_key(const float* arr, int n, int k,
                                  unsigned int* hist, unsigned int* cbuf,
                                  unsigned int* prefixSh, unsigned int* kSh, int t)
{
    if (t == 0) { *prefixSh = 0; *kSh = (unsigned int)k; }
    __syncthreads();
    for (int pass = 3; pass >= 0; --pass) {
        const int shift = pass * 8;
        hist[t] = 0;
        __syncthreads();
        const unsigned int prefix = *prefixSh;
        for (int i = t; i < n; i += 256) {
            const unsigned int u = f2u(arr[i]);
            bool cand = (pass == 3) || ((u >> (shift + 8)) == (prefix >> (shift + 8)));
            if (cand) atomicAdd(&hist[(u >> shift) & 0xFFu], 1u);
        }
        __syncthreads();
        cbuf[t] = hist[t];
        __syncthreads();
        for (int off = 1; off < 256; off <<= 1) {
            unsigned int v   = cbuf[t];
            unsigned int add = (t + off < 256) ? cbuf[t + off] : 0u;
            __syncthreads();
            cbuf[t] = v + add;
            __syncthreads();
        }
        const unsigned int kcur  = *kSh;
        const unsigned int here  = cbuf[t];
        const unsigned int above = (t < 255) ? cbuf[t + 1] : 0u;
        __syncthreads();
        if (here >= kcur && above < kcur) {
            *prefixSh = prefix | ((unsigned int)t << shift);
            *kSh = kcur - above;
        }
        __syncthreads();
    }
    return *prefixSh;
}

__global__ void __launch_bounds__(256) fixup_kernel(
    const float* __restrict__ X, const float* __restrict__ W,
    const float* __restrict__ bias, float* __restrict__ enc)
{
    const int row = blockIdx.x;
    float* p = enc + (size_t)row * N_HID;
    const int t = threadIdx.x;

    __shared__ float xrow[K_DIM];
    __shared__ float cval_s[CAP];
    __shared__ unsigned int hist[256], cbuf[256];
    __shared__ unsigned int prefixSh, kSh;
    __shared__ int nsel2, nfin;
    __shared__ int   sel_i[MAX_CAND];
    __shared__ float sel_v[MAX_CAND];

    for (int i = t; i < K_DIM; i += 256) xrow[i] = X[(size_t)row * K_DIM + i];
    if (t == 0) { nsel2 = 0; nfin = 0; }
    __syncthreads();

    const int cnt = g_ccnt[row];
    if (cnt >= RANK_SEL && cnt <= CAP) {
        for (int i = t; i < cnt; i += 256) cval_s[i] = g_cval[(size_t)row * CAP + i];
        __syncthreads();
        const unsigned int key = radix_key(cval_s, cnt, RANK_SEL,
                                           hist, cbuf, &prefixSh, &kSh, t);
        for (int i = t; i < cnt; i += 256) {
            if (f2u(cval_s[i]) >= key) {
                const int q = atomicAdd(&nsel2, 1);
                if (q < MAX_CAND) sel_i[q] = g_cidx[(size_t)row * CAP + i];
            }
        }
    } else {
        // fallback (statistically never taken): exact full-row recompute
        for (int n = t; n < N_HID; n += 256) {
            const float* wr = W + (size_t)n * K_DIM;
            float s = 0.0f;
            for (int k2 = 0; k2 < K_DIM; k2++) s = fmaf(xrow[k2], wr[k2], s);
            p[n] = s + bias[n];
        }
        __syncthreads();
        const unsigned int key = radix_key(p, N_HID, RANK_SEL,
                                           hist, cbuf, &prefixSh, &kSh, t);
        for (int i = t; i < N_HID; i += 256) {
            if (f2u(p[i]) >= key) {
                const int q = atomicAdd(&nsel2, 1);
                if (q < MAX_CAND) sel_i[q] = i;
            }
        }
        __syncthreads();
        float4 z4 = make_float4(0.f, 0.f, 0.f, 0.f);
        for (int i = t; i < N_HID / 4; i += 256) ((float4*)p)[i] = z4;  // re-zero
    }
    __syncthreads();
    const int nc = (nsel2 < MAX_CAND) ? nsel2 : MAX_CAND;

    // exact fp32 dot products for selected candidates (one warp per candidate)
    const int lane = t & 31, w = t >> 5;
    for (int i = w; i < nc; i += 8) {
        const float* wr = W + (size_t)sel_i[i] * K_DIM;
        float s = 0.0f;
#pragma unroll 4
        for (int j = lane; j < K_DIM; j += 32) s = fmaf(xrow[j], wr[j], s);
#pragma unroll
        for (int o = 16; o; o >>= 1) s += __shfl_xor_sync(0xFFFFFFFFu, s, o);
        if (lane == 0) sel_v[i] = s + bias[sel_i[i]];
    }
    __syncthreads();

    // exact rank; keep if fewer than K_SPARSE strictly greater (keeps ties)
    if (t < nc) {
        const float v = sel_v[t];
        int cg = 0;
        for (int j = 0; j < nc; j++) cg += (sel_v[j] > v);
        if (cg < K_SPARSE) {
            p[sel_i[t]] = v;
            const int q = atomicAdd(&nfin, 1);
            if (q < MAX_ACT) {
                g_idx[row * MAX_ACT + q] = sel_i[t];
                g_val[row * MAX_ACT + q] = v;
            }
        }
    }
    __syncthreads();
    if (t == 0) g_cnt[row] = (nfin > MAX_ACT) ? MAX_ACT : nfin;
}

// ---------------- sparse decoder ----------------
__global__ void __launch_bounds__(256) decode_kernel(
    const float* __restrict__ W, float* __restrict__ dec)
{
    const int row = blockIdx.x;
    const int t = threadIdx.x;

    __shared__ float coef[MAX_ACT];
    __shared__ int   jrow[MAX_ACT];

    const int c = g_cnt[row];
    if (t < MAX_ACT && t < c) {
        const int j = g_idx[row * MAX_ACT + t];
        jrow[t] = j;
        coef[t] = g_val[row * MAX_ACT + t] * g_invnorm[j];
    }
    __syncthreads();

    float a0 = 0.0f, a1 = 0.0f, a2 = 0.0f;
    for (int j = 0; j < c; ++j) {
        const float* w = W + (size_t)jrow[j] * K_DIM;
        const float cf = coef[j];
        a0 = fmaf(cf, w[t],       a0);
        a1 = fmaf(cf, w[t + 256], a1);
        a2 = fmaf(cf, w[t + 512], a2);
    }
    float* o = dec + (size_t)row * K_DIM;
    o[t] = a0; o[t + 256] = a1; o[t + 512] = a2;
}

// ---------------- launch ----------------
extern "C" void kernel_launch(void* const* d_in, const int* in_sizes, int n_in,
                              void* d_out, int out_size)
{
    const float* x = (const float*)d_in[0];
    const float* W = (const float*)d_in[1];
    const float* b = (const float*)d_in[2];
    float* out = (float*)d_out;

    float* dec = out;                               // [4096, 768]
    float* enc = out + (size_t)M_ROWS * K_DIM;      // [4096, 16384]

    convert_x_kernel<<<(M_ROWS * K_DIM + 255) / 256, 256>>>(x);
    convert_w_kernel<<<N_HID / 8, 256>>>(W);
    zero_kernel<<<4096, 256>>>((float4*)enc, M_ROWS * N_HID / 4);

    const int dyn_smem = NSTAGE * STAGE_TOT * 4;    // 61440 bytes
    cudaFuncSetAttribute(encode_gemm, cudaFuncAttributeMaxDynamicSharedMemorySize, dyn_smem);

    dim3 ggrid(M_ROWS / 128, N_HID / 128);          // x fast: consecutive CTAs share B tile
    encode_gemm<<<ggrid, 256, dyn_smem>>>(b);
    fixup_kernel<<<M_ROWS, 256>>>(x, W, b, enc);
    decode_kernel<<<M_ROWS, 256>>>(W, dec);
}

// round 9
// speedup vs baseline: 4.6064x; 1.0936x over previous
#include <cuda_runtime.h>
#include <cuda_bf16.h>
#include <cstdint>

#define M_ROWS 4096
#define N_HID  16384
#define K_DIM  768
#define K_SPARSE 32
#define MAX_ACT  64
#define MAX_CAND 96
#define RANK_SEL 64
#define CAP      1024
#define THRESH   2.0f

// GEMM tiling: 128x64 CTA tile, 8 warps of 32x32, BK=32 bf16, 3-stage pipeline
#define BKW 16                   // words (4B) per smem row
#define TS  20                   // padded word stride (conflict-free for ldmatrix)
#define NKTILE (K_DIM / 32)      // 24
#define STG_A (128 * TS)         // A stage words
#define STG_B (64 * TS)          // B stage words
#define STAGE_TOT (STG_A + STG_B)
#define NSTAGE 3

// ---------------- device scratch ----------------
__device__ __nv_bfloat16 X16[M_ROWS * K_DIM];
__device__ __nv_bfloat16 W16[N_HID * K_DIM];
__device__ int   g_ccnt[M_ROWS];
__device__ int   g_cidx[(size_t)M_ROWS * CAP];
__device__ float g_cval[(size_t)M_ROWS * CAP];
__device__ int   g_cnt[M_ROWS];
__device__ int   g_idx[M_ROWS * MAX_ACT];
__device__ float g_val[M_ROWS * MAX_ACT];
__device__ float g_invnorm[N_HID];

// ---------------- PTX helpers ----------------
__device__ __forceinline__ uint32_t cvta_shared(const void* p) {
    return (uint32_t)__cvta_generic_to_shared(p);
}
#define CP_ASYNC16(dst, src) \
    asm volatile("cp.async.cg.shared.global [%0], [%1], 16;\n" :: "r"(dst), "l"(src))
#define CP_COMMIT() asm volatile("cp.async.commit_group;\n" ::: "memory")
#define CP_WAIT1()  asm volatile("cp.async.wait_group 1;\n" ::: "memory")

#define LDSM_X4(r, addr) \
    asm volatile("ldmatrix.sync.aligned.m8n8.x4.shared.b16 {%0,%1,%2,%3}, [%4];" \
        : "=r"((r)[0]), "=r"((r)[1]), "=r"((r)[2]), "=r"((r)[3]) : "r"(addr))

__device__ __forceinline__ void mma_bf16(float* d, const uint32_t* a, const uint32_t* b)
{
    asm volatile(
        "mma.sync.aligned.m16n8k16.row.col.f32.bf16.bf16.f32 "
        "{%0,%1,%2,%3}, {%4,%5,%6,%7}, {%8,%9}, {%0,%1,%2,%3};\n"
        : "+f"(d[0]), "+f"(d[1]), "+f"(d[2]), "+f"(d[3])
        : "r"(a[0]), "r"(a[1]), "r"(a[2]), "r"(a[3]), "r"(b[0]), "r"(b[1]));
}

// ---------------- conversion kernels ----------------
__global__ void convert_x_kernel(const float* __restrict__ X)
{
    const int i = blockIdx.x * 256 + threadIdx.x;
    if (i < M_ROWS * K_DIM) X16[i] = __float2bfloat16(X[i]);
    if (i < M_ROWS) g_ccnt[i] = 0;
}

__global__ void convert_w_kernel(const float* __restrict__ W)
{
    const int row  = blockIdx.x * 8 + (threadIdx.x >> 5);
    const int lane = threadIdx.x & 31;
    const float* w = W + (size_t)row * K_DIM;
    float s = 0.0f;
    for (int i = lane; i < K_DIM; i += 32) {
        const float v = w[i];
        s = fmaf(v, v, s);
        W16[(size_t)row * K_DIM + i] = __float2bfloat16(v);
    }
#pragma unroll
    for (int o = 16; o; o >>= 1) s += __shfl_xor_sync(0xFFFFFFFFu, s, o);
    if (lane == 0) g_invnorm[row] = rsqrtf(s);
}

// ---------------- zero the encoded output region ----------------
__global__ void zero_kernel(float4* __restrict__ p, int n4)
{
    const float4 z = make_float4(0.f, 0.f, 0.f, 0.f);
    for (int i = blockIdx.x * blockDim.x + threadIdx.x; i < n4;
         i += gridDim.x * blockDim.x)
        p[i] = z;
}

// ---------------- encoder GEMM (bf16 mma.sync + ldmatrix, 3-stage) -------------
__device__ __forceinline__ void ldtile16(int m0, int n0, int kt,
                                         uint32_t* As, uint32_t* Bs, int t)
{
#pragma unroll
    for (int it = 0; it < 2; it++) {         // A: 128 rows x 4 granules
        const int g = t + it * 256;
        const int r = g >> 2;
        const int c = g & 3;
        CP_ASYNC16(cvta_shared(As + r * TS + c * 4),
                   X16 + (size_t)(m0 + r) * K_DIM + kt + c * 8);
    }
    {                                        // B: 64 rows x 4 granules
        const int r = t >> 2;
        const int c = t & 3;
        CP_ASYNC16(cvta_shared(Bs + r * TS + c * 4),
                   W16 + (size_t)(n0 + r) * K_DIM + kt + c * 8);
    }
}

__device__ __forceinline__ void cand_append(int row, int col, float v)
{
    if (v > THRESH) {
        const int q = atomicAdd(&g_ccnt[row], 1);
        if (q < CAP) {
            g_cidx[(size_t)row * CAP + q] = col;
            g_cval[(size_t)row * CAP + q] = v;
        }
    }
}

__global__ void __launch_bounds__(256, 3) encode_gemm(const float* __restrict__ bias)
{
    extern __shared__ uint32_t smem[];   // NSTAGE * STAGE_TOT words

    const int t    = threadIdx.x;
    const int lane = t & 31;
    const int wid  = t >> 5;
    const int m0   = blockIdx.x * 128;
    const int n0   = blockIdx.y * 64;
    const int wm   = (wid & 3) * 32;     // warp m offset (4 warps in M)
    const int wn   = (wid >> 2) * 32;    // warp n offset (2 warps in N)
    const int fg   = lane >> 2;
    const int fc   = lane & 3;

    // per-thread ldmatrix address offsets (bytes) within a stage
    const uint32_t aoff = ((wm + (lane & 15)) * TS + ((lane >> 4) << 2)) * 4;
    const uint32_t boff = ((wn + (lane & 7) + ((lane >> 4) << 3)) * TS
                           + (((lane >> 3) & 1) << 2)) * 4;

    float acc[2][4][4];
#pragma unroll
    for (int i = 0; i < 2; i++)
#pragma unroll
        for (int j = 0; j < 4; j++)
#pragma unroll
            for (int r = 0; r < 4; r++) acc[i][j][r] = 0.0f;

    // prologue: stages 0 and 1 in flight
    ldtile16(m0, n0, 0,  smem,             smem + STG_A,             t);
    CP_COMMIT();
    ldtile16(m0, n0, 32, smem + STAGE_TOT, smem + STAGE_TOT + STG_A, t);
    CP_COMMIT();

    int stage = 0, nstage = 2;
    for (int kt = 0; kt < NKTILE; kt++) {
        CP_WAIT1();                // tile kt's loads complete (<=1 newer pending)
        __syncthreads();           // publish loads; all warps past reads of refill stage

        if (kt + 2 < NKTILE) {
            uint32_t* sb = smem + nstage * STAGE_TOT;
            ldtile16(m0, n0, (kt + 2) * 32, sb, sb + STG_A, t);
        }
        CP_COMMIT();               // keep group count consistent (may be empty)

        const uint32_t Ab = cvta_shared(smem + stage * STAGE_TOT);
        const uint32_t Bb = Ab + STG_A * 4;
#pragma unroll
        for (int ks = 0; ks < BKW; ks += 8) {
            uint32_t a[2][4], b[2][4];
#pragma unroll
            for (int mi = 0; mi < 2; mi++)
                LDSM_X4(a[mi], Ab + aoff + (mi * 16 * TS + ks) * 4);
#pragma unroll
            for (int njp = 0; njp < 2; njp++)
                LDSM_X4(b[njp], Bb + boff + (njp * 16 * TS + ks) * 4);
#pragma unroll
            for (int mi = 0; mi < 2; mi++)
#pragma unroll
                for (int nj = 0; nj < 4; nj++)
                    mma_bf16(acc[mi][nj], a[mi], &b[nj >> 1][(nj & 1) * 2]);
        }

        stage  = (stage  + 1 == NSTAGE) ? 0 : stage + 1;
        nstage = (nstage + 1 == NSTAGE) ? 0 : nstage + 1;
    }

    // epilogue: threshold + append candidates (no dense store)
#pragma unroll
    for (int nj = 0; nj < 4; nj++) {
        const int col = n0 + wn + nj * 8 + fc * 2;
        const float b0 = bias[col], b1 = bias[col + 1];
#pragma unroll
        for (int mi = 0; mi < 2; mi++) {
            const int row = m0 + wm + mi * 16 + fg;
            cand_append(row,     col,     acc[mi][nj][0] + b0);
            cand_append(row,     col + 1, acc[mi][nj][1] + b1);
            cand_append(row + 8, col,     acc[mi][nj][2] + b0);
            cand_append(row + 8, col + 1, acc[mi][nj][3] + b1);
        }
    }
}

// ---------------- top-k fixup ----------------
__device__ __forceinline__ unsigned int f2u(float f)
{
    unsigned int b = __float_as_uint(f);
    return (b & 0x80000000u) ? ~b : (b | 0x80000000u);
}

// exact key of k-th largest over arr[0..n), 256-thread block collective
__device__ unsigned int radix_key(const float* arr, int n, int k,
                                  unsigned int* hist, unsigned int* cbuf,
                                  unsigned int* prefixSh, unsigned int* kSh, int t)
{
    if (t == 0) { *prefixSh = 0; *kSh = (unsigned int)k; }
    __syncthreads();
    for (int pass = 3; pass >= 0; --pass) {
        const int shift = pass * 8;
        hist[t] = 0;
        __syncthreads();
        const unsigned int prefix = *prefixSh;
        for (int i = t; i < n; i += 256) {
            const unsigned int u = f2u(arr[i]);
            bool cand = (pass == 3) || ((u >> (shift + 8)) == (prefix >> (shift + 8)));
            if (cand) atomicAdd(&hist[(u >> shift) & 0xFFu], 1u);
        }
        __syncthreads();
        cbuf[t] = hist[t];
        __syncthreads();
        for (int off = 1; off < 256; off <<= 1) {
            unsigned int v   = cbuf[t];
            unsigned int add = (t + off < 256) ? cbuf[t + off] : 0u;
            __syncthreads();
            cbuf[t] = v + add;
            __syncthreads();
        }
        const unsigned int kcur  = *kSh;
        const unsigned int here  = cbuf[t];
        const unsigned int above = (t < 255) ? cbuf[t + 1] : 0u;
        __syncthreads();
        if (here >= kcur && above < kcur) {
            *prefixSh = prefix | ((unsigned int)t << shift);
            *kSh = kcur - above;
        }
        __syncthreads();
    }
    return *prefixSh;
}

__global__ void __launch_bounds__(256) fixup_kernel(
    const float* __restrict__ X, const float* __restrict__ W,
    const float* __restrict__ bias, float* __restrict__ enc)
{
    const int row = blockIdx.x;
    float* p = enc + (size_t)row * N_HID;
    const int t = threadIdx.x;

    __shared__ float xrow[K_DIM];
    __shared__ float cval_s[CAP];
    __shared__ unsigned int hist[256], cbuf[256];
    __shared__ unsigned int prefixSh, kSh;
    __shared__ int nsel2, nfin;
    __shared__ int   sel_i[MAX_CAND];
    __shared__ float sel_v[MAX_CAND];

    for (int i = t; i < K_DIM; i += 256) xrow[i] = X[(size_t)row * K_DIM + i];
    if (t == 0) { nsel2 = 0; nfin = 0; }
    __syncthreads();

    const int cnt = g_ccnt[row];
    if (cnt >= RANK_SEL && cnt <= CAP) {
        for (int i = t; i < cnt; i += 256) cval_s[i] = g_cval[(size_t)row * CAP + i];
        __syncthreads();
        const unsigned int key = radix_key(cval_s, cnt, RANK_SEL,
                                           hist, cbuf, &prefixSh, &kSh, t);
        for (int i = t; i < cnt; i += 256) {
            if (f2u(cval_s[i]) >= key) {
                const int q = atomicAdd(&nsel2, 1);
                if (q < MAX_CAND) sel_i[q] = g_cidx[(size_t)row * CAP + i];
            }
        }
    } else {
        // fallback (statistically never taken): exact full-row recompute
        for (int n = t; n < N_HID; n += 256) {
            const float* wr = W + (size_t)n * K_DIM;
            float s = 0.0f;
            for (int k2 = 0; k2 < K_DIM; k2++) s = fmaf(xrow[k2], wr[k2], s);
            p[n] = s + bias[n];
        }
        __syncthreads();
        const unsigned int key = radix_key(p, N_HID, RANK_SEL,
                                           hist, cbuf, &prefixSh, &kSh, t);
        for (int i = t; i < N_HID; i += 256) {
            if (f2u(p[i]) >= key) {
                const int q = atomicAdd(&nsel2, 1);
                if (q < MAX_CAND) sel_i[q] = i;
            }
        }
        __syncthreads();
        float4 z4 = make_float4(0.f, 0.f, 0.f, 0.f);
        for (int i = t; i < N_HID / 4; i += 256) ((float4*)p)[i] = z4;  // re-zero
    }
    __syncthreads();
    const int nc = (nsel2 < MAX_CAND) ? nsel2 : MAX_CAND;

    // exact fp32 dot products for selected candidates (one warp per candidate)
    const int lane = t & 31, w = t >> 5;
    for (int i = w; i < nc; i += 8) {
        const float* wr = W + (size_t)sel_i[i] * K_DIM;
        float s = 0.0f;
#pragma unroll 4
        for (int j = lane; j < K_DIM; j += 32) s = fmaf(xrow[j], wr[j], s);
#pragma unroll
        for (int o = 16; o; o >>= 1) s += __shfl_xor_sync(0xFFFFFFFFu, s, o);
        if (lane == 0) sel_v[i] = s + bias[sel_i[i]];
    }
    __syncthreads();

    // exact rank; keep if fewer than K_SPARSE strictly greater (keeps ties)
    if (t < nc) {
        const float v = sel_v[t];
        int cg = 0;
        for (int j = 0; j < nc; j++) cg += (sel_v[j] > v);
        if (cg < K_SPARSE) {
            p[sel_i[t]] = v;
            const int q = atomicAdd(&nfin, 1);
            if (q < MAX_ACT) {
                g_idx[row * MAX_ACT + q] = sel_i[t];
                g_val[row * MAX_ACT + q] = v;
            }
        }
    }
    __syncthreads();
    if (t == 0) g_cnt[row] = (nfin > MAX_ACT) ? MAX_ACT : nfin;
}

// ---------------- sparse decoder ----------------
__global__ void __launch_bounds__(256) decode_kernel(
    const float* __restrict__ W, float* __restrict__ dec)
{
    const int row = blockIdx.x;
    const int t = threadIdx.x;

    __shared__ float coef[MAX_ACT];
    __shared__ int   jrow[MAX_ACT];

    const int c = g_cnt[row];
    if (t < MAX_ACT && t < c) {
        const int j = g_idx[row * MAX_ACT + t];
        jrow[t] = j;
        coef[t] = g_val[row * MAX_ACT + t] * g_invnorm[j];
    }
    __syncthreads();

    float a0 = 0.0f, a1 = 0.0f, a2 = 0.0f;
    for (int j = 0; j < c; ++j) {
        const float* w = W + (size_t)jrow[j] * K_DIM;
        const float cf = coef[j];
        a0 = fmaf(cf, w[t],       a0);
        a1 = fmaf(cf, w[t + 256], a1);
        a2 = fmaf(cf, w[t + 512], a2);
    }
    float* o = dec + (size_t)row * K_DIM;
    o[t] = a0; o[t + 256] = a1; o[t + 512] = a2;
}

// ---------------- launch ----------------
extern "C" void kernel_launch(void* const* d_in, const int* in_sizes, int n_in,
                              void* d_out, int out_size)
{
    const float* x = (const float*)d_in[0];
    const float* W = (const float*)d_in[1];
    const float* b = (const float*)d_in[2];
    float* out = (float*)d_out;

    float* dec = out;                               // [4096, 768]
    float* enc = out + (size_t)M_ROWS * K_DIM;      // [4096, 16384]

    convert_x_kernel<<<(M_ROWS * K_DIM + 255) / 256, 256>>>(x);
    convert_w_kernel<<<N_HID / 8, 256>>>(W);
    zero_kernel<<<4096, 256>>>((float4*)enc, M_ROWS * N_HID / 4);

    const int dyn_smem = NSTAGE * STAGE_TOT * 4;    // 46080 bytes
    cudaFuncSetAttribute(encode_gemm, cudaFuncAttributeMaxDynamicSharedMemorySize, dyn_smem);

    dim3 ggrid(M_ROWS / 128, N_HID / 64);           // x fast: consecutive CTAs share B tile
    encode_gemm<<<ggrid, 256, dyn_smem>>>(b);
    fixup_kernel<<<M_ROWS, 256>>>(x, W, b, enc);
    decode_kernel<<<M_ROWS, 256>>>(W, dec);
}